// round 15
// baseline (speedup 1.0000x reference)
#include <cuda_runtime.h>
#include <cuda_bf16.h>
#include <math.h>
#include <stdint.h>

#define B_   128
#define T_   512
#define H_   512
#define G_   2048
#define DIN_ 8
#define HOR_ 64
#define MQ_  5
#define DFF_ 7
#define NBLK 128

typedef unsigned long long u64;

// ---------------- scratch (device globals; no allocations) ----------------
__device__ float g_gates0[2][T_][B_][G_];    // precomputed layer-0 input gates
__device__ float g_gates1[2][T_][B_][G_];    // precomputed layer-1 input gates
__device__ float g_c[2][2][B_][H_];          // final cell states [layer][dir]
__device__ float g_h0fin[2][B_][H_];         // layer-0 final h per dir (fp32)
__device__ float g_h1fin[2][B_][H_];         // layer-1 final h per dir (fp32)
__device__ float g_dec_h0[2][B_][H_];
__device__ float g_dec_c0[B_][H_];
__device__ float g_dec_h1[2][B_][H_];
__device__ float g_dec_c1[B_][H_];
__device__ float g_decx[B_][DIN_];           // decoder input vector [y_fb, fut]
__device__ unsigned g_bar_cnt;               // decoder barrier
__device__ unsigned g_bar_gen;
__device__ unsigned g_ebar_cnt[4 * 32];      // encoder per-(dir,btile) barriers
__device__ unsigned g_ebar_gen[4 * 32];

// bf16 hi/lo split activations (enc-L0 h sequence; also gates1_mma's A input)
__device__ __nv_bfloat16 g_Ah[T_ * B_][1024];
__device__ __nv_bfloat16 g_Al[T_ * B_][1024];
// layer-1 h ping-pong, bf16 hi/lo
__device__ __nv_bfloat16 g_h1h[2][2][B_][H_];
__device__ __nv_bfloat16 g_h1l[2][2][B_][H_];
// gates1 weights, bf16 hi/lo
__device__ __nv_bfloat16 g_Bh[2][G_][1024];
__device__ __nv_bfloat16 g_Bl[2][G_][1024];

// ---------------- grid barriers (R8 mechanism: weak volatile poll) --------
__device__ __forceinline__ void grid_barrier()          // decoder, 128 CTAs
{
    __syncthreads();
    if (threadIdx.x == 0) {
        volatile unsigned* genp = &g_bar_gen;
        unsigned gen = *genp;
        __threadfence();
        if (atomicAdd(&g_bar_cnt, 1u) == NBLK - 1u) {
            g_bar_cnt = 0u;
            __threadfence();
            *genp = gen + 1u;
        } else {
            while (*genp == gen) { }
        }
        __threadfence();
    }
    __syncthreads();
}

__device__ __forceinline__ void grid_barrier_grp(int g)  // encoder, 64 CTAs/group
{
    __syncthreads();
    if (threadIdx.x == 0) {
        volatile unsigned* genp = &g_ebar_gen[g * 32];
        unsigned gen = *genp;
        __threadfence();
        if (atomicAdd(&g_ebar_cnt[g * 32], 1u) == 63u) {
            g_ebar_cnt[g * 32] = 0u;
            __threadfence();
            *genp = gen + 1u;
        } else {
            while (*genp == gen) { }
        }
        __threadfence();
    }
    __syncthreads();
}

// ---------------- packed fp32x2 helpers (decoder SIMT path) ----------------
__device__ __forceinline__ void ffma2(u64& d, u64 a, u64 b) {
    asm("fma.rn.f32x2 %0, %1, %2, %0;" : "+l"(d) : "l"(a), "l"(b));
}
__device__ __forceinline__ u64 bcast2(float v) {
    u64 r;
    asm("mov.b64 %0, {%1, %1};" : "=l"(r) : "f"(v));
    return r;
}
__device__ __forceinline__ void unpack2(u64 v, float& lo, float& hi) {
    asm("mov.b64 {%0, %1}, %2;" : "=f"(lo), "=f"(hi) : "l"(v));
}

// ---------------- fast transcendentals ----------------
__device__ __forceinline__ float sigm_(float x) {
    return __fdividef(1.f, 1.f + __expf(-x));
}
__device__ __forceinline__ float tanh_(float x) {
    return __fdividef(2.f, 1.f + __expf(-2.f * x)) - 1.f;
}

// ---------------- mma.sync / ldmatrix helpers ----------------
__device__ __forceinline__ uint32_t smem_u32(const void* p) {
    uint32_t a;
    asm("{ .reg .u64 t; cvta.to.shared.u64 t, %1; cvt.u32.u64 %0, t; }"
        : "=r"(a) : "l"(p));
    return a;
}
__device__ __forceinline__ void ldsm4(uint32_t a, uint32_t& r0, uint32_t& r1,
                                      uint32_t& r2, uint32_t& r3) {
    asm volatile("ldmatrix.sync.aligned.m8n8.x4.shared.b16 {%0,%1,%2,%3}, [%4];"
                 : "=r"(r0), "=r"(r1), "=r"(r2), "=r"(r3) : "r"(a));
}
__device__ __forceinline__ void mma_bf16(float* c, const uint32_t* a, const uint32_t* b) {
    asm volatile(
        "mma.sync.aligned.m16n8k16.row.col.f32.bf16.bf16.f32 "
        "{%0,%1,%2,%3}, {%4,%5,%6,%7}, {%8,%9}, {%0,%1,%2,%3};"
        : "+f"(c[0]), "+f"(c[1]), "+f"(c[2]), "+f"(c[3])
        : "r"(a[0]), "r"(a[1]), "r"(a[2]), "r"(a[3]), "r"(b[0]), "r"(b[1]));
}

// ---------------- layer-0 input gates: one-shot tiny-K GEMM ----------------
__global__ __launch_bounds__(256) void gates0_gemm(
    const float* __restrict__ X, const float* __restrict__ w_ih)
{
    __shared__ float xs_[B_][DIN_];
    const int t = blockIdx.x, dir = blockIdx.y;
    const int tid = threadIdx.x;
    for (int e = tid; e < B_ * DIN_; e += 256) {
        int b = e >> 3, k = e & 7;
        xs_[b][k] = __ldg(X + ((long)b * T_ + t) * DIN_ + k);
    }
    __syncthreads();
    const float* w = w_ih + (long)dir * G_ * DIN_;
    for (int g = tid; g < G_; g += 256) {
        float4 w0 = *reinterpret_cast<const float4*>(w + g * DIN_);
        float4 w1 = *reinterpret_cast<const float4*>(w + g * DIN_ + 4);
        float* op = &g_gates0[dir][t][0][0];
        for (int b = 0; b < B_; ++b) {
            const float* xb = xs_[b];
            float acc = xb[0] * w0.x + xb[1] * w0.y + xb[2] * w0.z + xb[3] * w0.w
                      + xb[4] * w1.x + xb[5] * w1.y + xb[6] * w1.z + xb[7] * w1.w;
            op[(long)b * G_ + g] = acc;
        }
    }
}

// -------- fp32 -> bf16 hi/lo conversion for gates1 weights ----------------
__global__ __launch_bounds__(256) void convB_kernel(const float* __restrict__ w_ih1)
{
    const long npairs = (long)2 * G_ * 512;
    __nv_bfloat16* bh = &g_Bh[0][0][0];
    __nv_bfloat16* bl = &g_Bl[0][0][0];
    for (long p = (long)blockIdx.x * 256 + threadIdx.x; p < npairs;
         p += (long)gridDim.x * 256) {
        float2 v = *reinterpret_cast<const float2*>(w_ih1 + p * 2);
        __nv_bfloat16 h0 = __float2bfloat16(v.x);
        __nv_bfloat16 l0 = __float2bfloat16(v.x - __bfloat162float(h0));
        __nv_bfloat16 h1 = __float2bfloat16(v.y);
        __nv_bfloat16 l1 = __float2bfloat16(v.y - __bfloat162float(h1));
        *reinterpret_cast<__nv_bfloat162*>(bh + p * 2) = __nv_bfloat162(h0, h1);
        *reinterpret_cast<__nv_bfloat162*>(bl + p * 2) = __nv_bfloat162(l0, l1);
    }
}

// =========== persistent mma-based encoder layer (layer = 0 or 1) ==========
// 256 CTAs, 2/SM. CTA = 64 batch x 32 gate-cols (8 j x 4 gates), K=512/step.
// W_hh hi/lo resident in SMEM; A streamed in 8 double-buffered 64-k chunks.
// 8 warps = 4M x 2N (warp: 16 x 16). Barrier = 64-CTA (dir,btile) group.
#define E2_W_H 0
#define E2_W_L 33280
#define E2_A   66560
#define E2_AB  9216
#define E2_C   103424
#define ENC_SMEM 112640

template<int LAYER>
__global__ __launch_bounds__(256, 2) void enc_mma_persist(
    const float* __restrict__ w_hh, const float* __restrict__ bias)
{
    extern __shared__ __align__(16) char esm[];
    __nv_bfloat16* Wh = reinterpret_cast<__nv_bfloat16*>(esm + E2_W_H);
    __nv_bfloat16* Wl = reinterpret_cast<__nv_bfloat16*>(esm + E2_W_L);
    float* Cb = reinterpret_cast<float*>(esm + E2_C);

    const int tid = threadIdx.x, lane = tid & 31, wid = tid >> 5;
    const int warp_m = wid & 3, warp_n = wid >> 2;
    const int bid = blockIdx.x;
    const int dir = bid >> 7, rem = bid & 127;
    const int btile = rem >> 6, jt = rem & 63;
    const int b0 = btile * 64, j0 = jt * 8;
    const int grp = dir * 2 + btile;

    // ---- one-time W_hh load + hi/lo split (32 gate-cols x 512) ----
    const float* wsrc = w_hh + (long)dir * G_ * H_;
    for (int idx = tid; idx < 32 * 512; idx += 256) {
        int n = idx >> 9, k = idx & 511;
        int gc = (n >> 3) * 512 + j0 + (n & 7);
        float v = __ldg(wsrc + (long)gc * H_ + k);
        __nv_bfloat16 h = __float2bfloat16(v);
        Wh[n * 520 + k] = h;
        Wl[n * 520 + k] = __float2bfloat16(v - __bfloat162float(h));
    }

    // ---- pointwise mapping: pb = batch-local (0..63), jq -> j-pair ----
    const int pb = tid >> 2, jq = tid & 3;
    const float* bp = bias + dir * G_ + j0 + jq * 2;
    float2 bI = __ldg((const float2*)(bp));
    float2 bF = __ldg((const float2*)(bp + 512));
    float2 bG = __ldg((const float2*)(bp + 1024));
    float2 bO = __ldg((const float2*)(bp + 1536));
    float cst[2] = {0.f, 0.f};

    // ---- ldmatrix lane offsets ----
    uint32_t WhB = smem_u32(Wh), WlB = smem_u32(Wl);
    const uint32_t aRow = (uint32_t)((warp_m * 16 + (lane & 15)) * 144
                                     + (lane >> 4) * 16);
    const uint32_t bOff4 = (uint32_t)((warp_n * 16 + ((lane >> 4) & 1) * 8
                                       + (lane & 7)) * 1040
                                      + ((lane >> 3) & 1) * 16);

    const float* gatesrc = (LAYER == 0 ? &g_gates0[0][0][0][0]
                                       : &g_gates1[0][0][0][0])
                         + (long)dir * T_ * B_ * G_;
    __syncthreads();

    for (int s = 0; s < T_; ++s) {
        const int t = dir ? (T_ - 1 - s) : s;
        const float* gp = gatesrc + ((long)t * B_ + b0 + pb) * G_ + j0 + jq * 2;
        float2 gI = __ldg((const float2*)(gp));
        float2 gF = __ldg((const float2*)(gp + 512));
        float2 gG = __ldg((const float2*)(gp + 1024));
        float2 gO = __ldg((const float2*)(gp + 1536));

        float acc[2][4] = {};
        if (s > 0) {
            const __nv_bfloat16 *pAh, *pAl;
            long apitch;
            if (LAYER == 0) {
                const int tp = dir ? t + 1 : t - 1;
                pAh = &g_Ah[tp * 128 + b0][dir * 512];
                pAl = &g_Al[tp * 128 + b0][dir * 512];
                apitch = 1024;
            } else {
                pAh = &g_h1h[s & 1][dir][b0][0];
                pAl = &g_h1l[s & 1][dir][b0][0];
                apitch = 512;
            }
            uint4 stg[4];
            auto stage = [&](int kc) {
                #pragma unroll
                for (int i = 0; i < 4; ++i) {
                    int idx = tid + i * 256;
                    int term = idx >> 9, rem2 = idx & 511;
                    int row = rem2 >> 3, c8 = rem2 & 7;
                    const __nv_bfloat16* src =
                        (term ? pAl : pAh) + (long)row * apitch + kc * 64 + c8 * 8;
                    stg[i] = __ldcg(reinterpret_cast<const uint4*>(src));
                }
            };
            auto commitA = [&](int buf) {
                #pragma unroll
                for (int i = 0; i < 4; ++i) {
                    int idx = tid + i * 256;
                    int term = idx >> 9, rem2 = idx & 511;
                    int row = rem2 >> 3, c8 = rem2 & 7;
                    *reinterpret_cast<uint4*>(
                        esm + E2_A + (buf * 2 + term) * E2_AB + row * 144 + c8 * 16)
                        = stg[i];
                }
            };
            stage(0);
            commitA(0);
            __syncthreads();
            #pragma unroll 1
            for (int kc = 0; kc < 8; ++kc) {
                const int buf = kc & 1;
                if (kc < 7) stage(kc + 1);
                const uint32_t AhB = smem_u32(esm + E2_A + (buf * 2) * E2_AB);
                const uint32_t AlB = AhB + E2_AB;
                #pragma unroll
                for (int ks = 0; ks < 4; ++ks) {
                    const uint32_t wko = kc * 128 + ks * 32;
                    uint32_t ah[4], al[4], bh[2][2], bl[2][2];
                    ldsm4(AhB + aRow + ks * 32, ah[0], ah[1], ah[2], ah[3]);
                    ldsm4(AlB + aRow + ks * 32, al[0], al[1], al[2], al[3]);
                    ldsm4(WhB + bOff4 + wko, bh[0][0], bh[0][1], bh[1][0], bh[1][1]);
                    ldsm4(WlB + bOff4 + wko, bl[0][0], bl[0][1], bl[1][0], bl[1][1]);
                    #pragma unroll
                    for (int ni = 0; ni < 2; ++ni) {
                        mma_bf16(acc[ni], ah, bh[ni]);
                        mma_bf16(acc[ni], ah, bl[ni]);
                        mma_bf16(acc[ni], al, bh[ni]);
                    }
                }
                if (kc < 7) commitA(buf ^ 1);
                __syncthreads();
            }
        }
        // ---- epilogue: dump acc frags to Cbuf (64 x 32, pitch 36) ----
        {
            const int row = warp_m * 16 + (lane >> 2);
            #pragma unroll
            for (int ni = 0; ni < 2; ++ni) {
                const int col = warp_n * 16 + ni * 8 + (lane & 3) * 2;
                *reinterpret_cast<float2*>(&Cb[row * 36 + col]) =
                    make_float2(acc[ni][0], acc[ni][1]);
                *reinterpret_cast<float2*>(&Cb[(row + 8) * 36 + col]) =
                    make_float2(acc[ni][2], acc[ni][3]);
            }
        }
        __syncthreads();
        // ---- pointwise LSTM cell + h split/write (2 cells/thread) ----
        {
            __align__(4) __nv_bfloat16 hh[2], hl[2];
            float hv[2];
            const float* gIv = (const float*)&gI;
            const float* gFv = (const float*)&gF;
            const float* gGv = (const float*)&gG;
            const float* gOv = (const float*)&gO;
            const float* bIv = (const float*)&bI;
            const float* bFv = (const float*)&bF;
            const float* bGv = (const float*)&bG;
            const float* bOv = (const float*)&bO;
            #pragma unroll
            for (int q = 0; q < 2; ++q) {
                const int jl = jq * 2 + q;
                float iv = Cb[pb * 36 + jl]      + gIv[q] + bIv[q];
                float fv = Cb[pb * 36 + 8 + jl]  + gFv[q] + bFv[q];
                float gv = Cb[pb * 36 + 16 + jl] + gGv[q] + bGv[q];
                float ov = Cb[pb * 36 + 24 + jl] + gOv[q] + bOv[q];
                float i_ = sigm_(iv), f_ = sigm_(fv), g_ = tanh_(gv), o_ = sigm_(ov);
                float c = f_ * cst[q] + i_ * g_;
                cst[q] = c;
                float h = o_ * tanh_(c);
                hv[q] = h;
                hh[q] = __float2bfloat16(h);
                hl[q] = __float2bfloat16(h - __bfloat162float(hh[q]));
            }
            if (LAYER == 0) {
                *reinterpret_cast<uint32_t*>(&g_Ah[t * 128 + b0 + pb][dir * 512 + j0 + jq * 2])
                    = *reinterpret_cast<uint32_t*>(hh);
                *reinterpret_cast<uint32_t*>(&g_Al[t * 128 + b0 + pb][dir * 512 + j0 + jq * 2])
                    = *reinterpret_cast<uint32_t*>(hl);
                if (s == T_ - 1)
                    *reinterpret_cast<float2*>(&g_h0fin[dir][b0 + pb][j0 + jq * 2]) =
                        make_float2(hv[0], hv[1]);
            } else {
                *reinterpret_cast<uint32_t*>(&g_h1h[(s + 1) & 1][dir][b0 + pb][j0 + jq * 2])
                    = *reinterpret_cast<uint32_t*>(hh);
                *reinterpret_cast<uint32_t*>(&g_h1l[(s + 1) & 1][dir][b0 + pb][j0 + jq * 2])
                    = *reinterpret_cast<uint32_t*>(hl);
                if (s == T_ - 1)
                    *reinterpret_cast<float2*>(&g_h1fin[dir][b0 + pb][j0 + jq * 2]) =
                        make_float2(hv[0], hv[1]);
            }
        }
        grid_barrier_grp(grp);
    }
    *reinterpret_cast<float2*>(&g_c[LAYER][dir][b0 + pb][j0 + jq * 2]) =
        make_float2(cst[0], cst[1]);
}

// ======== gates1 via mma.sync bf16: D[128,128] = A[128,1024] @ W^T =========
#define PITCH 40

__global__ __launch_bounds__(256) void gates1_mma()
{
    __shared__ __align__(16) __nv_bfloat16 smem4[4][128 * PITCH];
    const int tid = threadIdx.x;
    const int wid = tid >> 5, lane = tid & 31;
    const int n0 = blockIdx.x * 128, r0 = blockIdx.y * 128, dir = blockIdx.z;
    const int warp_m = wid & 1, warp_n = wid >> 1;

    const __nv_bfloat16* srcs[4] = {
        &g_Ah[r0][0], &g_Al[r0][0], &g_Bh[dir][n0][0], &g_Bl[dir][n0][0] };
    uint32_t sb[4] = { smem_u32(smem4[0]), smem_u32(smem4[1]),
                       smem_u32(smem4[2]), smem_u32(smem4[3]) };

    uint32_t aOff[4], bOff4[2];
    #pragma unroll
    for (int mi = 0; mi < 4; ++mi)
        aOff[mi] = (uint32_t)((warp_m * 64 + mi * 16 + (lane & 15)) * (PITCH * 2)
                              + (lane >> 4) * 16);
    #pragma unroll
    for (int p = 0; p < 2; ++p)
        bOff4[p] = (uint32_t)((warp_n * 32 + (2 * p + ((lane >> 4) & 1)) * 8
                               + (lane & 7)) * (PITCH * 2)
                              + ((lane >> 3) & 1) * 16);

    uint2 stg[16];
    auto stage = [&](int kbase) {
        #pragma unroll
        for (int i = 0; i < 16; ++i) {
            int idx = i * 256 + tid;
            int tI = idx >> 10, row = (idx >> 3) & 127, c = idx & 7;
            stg[i] = *reinterpret_cast<const uint2*>(
                srcs[tI] + (long)row * 1024 + kbase + c * 4);
        }
    };
    auto commit = [&]() {
        #pragma unroll
        for (int i = 0; i < 16; ++i) {
            int idx = i * 256 + tid;
            int tI = idx >> 10, row = (idx >> 3) & 127, c = idx & 7;
            *reinterpret_cast<uint2*>(&smem4[tI][row * PITCH + c * 4]) = stg[i];
        }
    };

    float acc[4][4][4];
    #pragma unroll
    for (int mi = 0; mi < 4; ++mi)
        #pragma unroll
        for (int ni = 0; ni < 4; ++ni)
            #pragma unroll
            for (int q = 0; q < 4; ++q) acc[mi][ni][q] = 0.f;

    stage(0);
    commit();
    __syncthreads();
    #pragma unroll 1
    for (int kc = 0; kc < 32; ++kc) {
        if (kc < 31) stage((kc + 1) * 32);
        #pragma unroll
        for (int ks = 0; ks < 2; ++ks) {
            const uint32_t kb = ks * 32;
            uint32_t ah[4][4], al[4][4], bh[4][2], bl[4][2];
            #pragma unroll
            for (int mi = 0; mi < 4; ++mi) {
                ldsm4(sb[0] + aOff[mi] + kb, ah[mi][0], ah[mi][1], ah[mi][2], ah[mi][3]);
                ldsm4(sb[1] + aOff[mi] + kb, al[mi][0], al[mi][1], al[mi][2], al[mi][3]);
            }
            ldsm4(sb[2] + bOff4[0] + kb, bh[0][0], bh[0][1], bh[1][0], bh[1][1]);
            ldsm4(sb[2] + bOff4[1] + kb, bh[2][0], bh[2][1], bh[3][0], bh[3][1]);
            ldsm4(sb[3] + bOff4[0] + kb, bl[0][0], bl[0][1], bl[1][0], bl[1][1]);
            ldsm4(sb[3] + bOff4[1] + kb, bl[2][0], bl[2][1], bl[3][0], bl[3][1]);
            #pragma unroll
            for (int mi = 0; mi < 4; ++mi)
                #pragma unroll
                for (int ni = 0; ni < 4; ++ni) {
                    mma_bf16(acc[mi][ni], ah[mi], bh[ni]);
                    mma_bf16(acc[mi][ni], ah[mi], bl[ni]);
                    mma_bf16(acc[mi][ni], al[mi], bh[ni]);
                }
        }
        __syncthreads();
        if (kc < 31) { commit(); __syncthreads(); }
    }

    float* ob = &g_gates1[dir][0][0][0];
    const int group = lane >> 2, tig = lane & 3;
    #pragma unroll
    for (int mi = 0; mi < 4; ++mi) {
        const long row = r0 + warp_m * 64 + mi * 16 + group;
        #pragma unroll
        for (int ni = 0; ni < 4; ++ni) {
            const int col = n0 + warp_n * 32 + ni * 8 + tig * 2;
            *reinterpret_cast<float2*>(ob + row * G_ + col) =
                make_float2(acc[mi][ni][0], acc[mi][ni][1]);
            *reinterpret_cast<float2*>(ob + (row + 8) * G_ + col) =
                make_float2(acc[mi][ni][2], acc[mi][ni][3]);
        }
    }
}

// -------- SIMT segment accumulate, unpipelined (decoder K=8 seg only) -----
template<int BT>
__device__ __forceinline__ void seg_accum(
    float (*a_s)[BT + 4], float (*w_s)[33],
    const float* __restrict__ xp, int xs, int use_ldcg,
    const float* __restrict__ wp, int ws, int K,
    int b0, int j0, u64 acc2[BT / 16][4])
{
    const int tid = threadIdx.x, tx = tid & 31, ty = tid >> 5;
    constexpr int P = BT / 16;
    for (int k0 = 0; k0 < K; k0 += 32) {
        __syncthreads();
        #pragma unroll
        for (int i = 0; i < (BT * 32) / 256; ++i) {
            int e = tid + i * 256;
            int r = e >> 5, kk = e & 31, kg = k0 + kk;
            float v = 0.f;
            if (kg < K) {
                const float* p = xp + (long)(b0 + r) * xs + kg;
                v = use_ldcg ? __ldcg(p) : __ldg(p);
            }
            a_s[kk][r] = v;
        }
        #pragma unroll
        for (int i = 0; i < 16; ++i) {
            int e = tid + i * 256;
            int c = e >> 5, kk = e & 31, kg = k0 + kk;
            float v = 0.f;
            if (kg < K) {
                int gc = j0 + (c >> 5) * 512 + (c & 31);
                v = __ldg(wp + (long)gc * ws + kg);
            }
            w_s[c][kk] = v;
        }
        __syncthreads();
        #pragma unroll
        for (int kk = 0; kk < 32; ++kk) {
            u64 av[P];
            #pragma unroll
            for (int p = 0; p < P; ++p)
                av[p] = *reinterpret_cast<const u64*>(&a_s[kk][ty * (2 * P) + 2 * p]);
            #pragma unroll
            for (int gi = 0; gi < 4; ++gi) {
                u64 wv2 = bcast2(w_s[gi * 32 + tx][kk]);
                #pragma unroll
                for (int p = 0; p < P; ++p)
                    ffma2(acc2[p][gi], av[p], wv2);
            }
        }
    }
}

// -------- pipelined K=512 segment (decoder, BT=16) ------------------------
__device__ __forceinline__ void seg16_pipe(
    float (*a_s)[32][20], float (*w_s)[128][33],
    const float* __restrict__ xp, int xs,
    const float* __restrict__ wp, int ws,
    int b0, int j0, u64 acc2[1][4])
{
    const int tid = threadIdx.x, tx = tid & 31, ty = tid >> 5;
    int aofs[2], gcofs[16];
    #pragma unroll
    for (int i = 0; i < 2; ++i) {
        int e = tid + i * 256;
        aofs[i] = (b0 + (e >> 5)) * xs + (e & 31);
    }
    #pragma unroll
    for (int i = 0; i < 16; ++i) {
        int c = ty + 8 * i;
        gcofs[i] = (j0 + (c >> 5) * 512 + (c & 31)) * ws + tx;
    }
    float ar[2], wr[16];
    auto stage = [&](int kt) {
        const int ko = kt * 32;
        ar[0] = __ldcg(xp + aofs[0] + ko);
        ar[1] = __ldcg(xp + aofs[1] + ko);
        #pragma unroll
        for (int i = 0; i < 16; ++i)
            wr[i] = __ldg(wp + gcofs[i] + ko);
    };
    auto commit = [&](int buf) {
        #pragma unroll
        for (int i = 0; i < 2; ++i) {
            int e = tid + i * 256;
            a_s[buf][e & 31][e >> 5] = ar[i];
        }
        #pragma unroll
        for (int i = 0; i < 16; ++i)
            w_s[buf][ty + 8 * i][tx] = wr[i];
    };
    __syncthreads();
    stage(0);
    commit(0);
    __syncthreads();
    #pragma unroll 1
    for (int kt = 0; kt < 16; ++kt) {
        const int buf = kt & 1;
        if (kt < 15) stage(kt + 1);
        #pragma unroll
        for (int kk = 0; kk < 32; ++kk) {
            u64 av = *reinterpret_cast<const u64*>(&a_s[buf][kk][2 * ty]);
            #pragma unroll
            for (int gi = 0; gi < 4; ++gi) {
                u64 w2 = bcast2(w_s[buf][gi * 32 + tx][kk]);
                ffma2(acc2[0][gi], av, w2);
            }
        }
        if (kt < 15) commit(buf ^ 1);
        __syncthreads();
    }
}

// ---------------- bridge: elu(h/c_flat @ Wbᵀ + bb) -> decoder init ---------
__global__ __launch_bounds__(256) void bridge_kernel(
    const float* __restrict__ wb, const float* __restrict__ bb)
{
    __shared__ float in_s[32][33], w_s2[32][33];
    const int tid = threadIdx.x, tx = tid & 31, ty = tid >> 5;
    const int b0 = blockIdx.x * 32, m0 = blockIdx.y * 32, z = blockIdx.z;
    const float* srcs[4];
    if (z == 0) {
        srcs[0] = &g_h0fin[0][0][0]; srcs[1] = &g_h0fin[1][0][0];
        srcs[2] = &g_h1fin[0][0][0]; srcs[3] = &g_h1fin[1][0][0];
    } else {
        srcs[0] = &g_c[0][0][0][0]; srcs[1] = &g_c[0][1][0][0];
        srcs[2] = &g_c[1][0][0][0]; srcs[3] = &g_c[1][1][0][0];
    }
    float acc[4] = {0.f, 0.f, 0.f, 0.f};
    for (int k0 = 0; k0 < 2048; k0 += 32) {
        __syncthreads();
        const float* src = srcs[k0 >> 9];
        const int kl = k0 & 511;
        #pragma unroll
        for (int i = 0; i < 4; ++i) {
            int e = tid + i * 256;
            int r = e >> 5, kk = e & 31;
            in_s[r][kk] = src[(long)(b0 + r) * H_ + kl + kk];
            w_s2[r][kk] = wb[(long)(m0 + r) * 2048 + k0 + kk];
        }
        __syncthreads();
        #pragma unroll
        for (int kk = 0; kk < 32; ++kk) {
            float wv = w_s2[tx][kk];
            #pragma unroll
            for (int bi = 0; bi < 4; ++bi)
                acc[bi] = fmaf(in_s[ty * 4 + bi][kk], wv, acc[bi]);
        }
    }
    const int m = m0 + tx;
    #pragma unroll
    for (int bi = 0; bi < 4; ++bi) {
        int b = b0 + ty * 4 + bi;
        float v = acc[bi] + bb[m];
        v = (v > 0.f) ? v : expm1f(v);
        if (z == 0) {
            if (m < 512) g_dec_h0[0][b][m] = v; else g_dec_h1[0][b][m - 512] = v;
        } else {
            if (m < 512) g_dec_c0[b][m] = v;    else g_dec_c1[b][m - 512] = v;
        }
    }
}

// ---------------- decoder: persistent, 64 steps ----------------------------
__global__ __launch_bounds__(256, 1) void dec_persist(
    const float* __restrict__ X, const float* __restrict__ fut,
    const float* __restrict__ dwih0, const float* __restrict__ dwhh0,
    const float* __restrict__ db0,
    const float* __restrict__ dwih1, const float* __restrict__ dwhh1,
    const float* __restrict__ db1,
    const float* __restrict__ wo, const float* __restrict__ bo,
    float* __restrict__ out)
{
    __shared__ __align__(16) float a_s2[2][32][20];
    __shared__ __align__(16) float w_s2[2][128][33];
    __shared__ float red[8][MQ_];
    const int bid = blockIdx.x, tid = threadIdx.x;
    const int tx = tid & 31, ty = tid >> 5;
    const int b0 = (bid >> 4) * 16, j0 = (bid & 15) * 32;
    const int j = j0 + tx;

    if (tid < DIN_)
        g_decx[bid][tid] = (tid == 0)
            ? __ldg(X + (long)bid * T_ * DIN_ + (T_ - 1) * DIN_)
            : __ldg(fut + (long)bid * HOR_ * DFF_ + (tid - 1));

    const float b0I = __ldg(db0 + j),        b0F = __ldg(db0 + 512 + j),
                b0G = __ldg(db0 + 1024 + j), b0O = __ldg(db0 + 1536 + j);
    const float b1I = __ldg(db1 + j),        b1F = __ldg(db1 + 512 + j),
                b1G = __ldg(db1 + 1024 + j), b1O = __ldg(db1 + 1536 + j);
    float c0[2], c1[2];
    #pragma unroll
    for (int bi = 0; bi < 2; ++bi) {
        c0[bi] = g_dec_c0[b0 + ty * 2 + bi][j];
        c1[bi] = g_dec_c1[b0 + ty * 2 + bi][j];
    }
    grid_barrier();

    for (int s = 0; s < HOR_; ++s) {
        {
            u64 acc2[1][4] = {};
            seg_accum<16>(a_s2[0], w_s2[0], &g_decx[0][0], DIN_, 1,
                          dwih0, DIN_, DIN_, b0, j0, acc2);
            seg16_pipe(a_s2, w_s2, &g_dec_h0[s & 1][0][0], H_,
                       dwhh0, H_, b0, j0, acc2);
            float acc[2][4];
            #pragma unroll
            for (int gi = 0; gi < 4; ++gi)
                unpack2(acc2[0][gi], acc[0][gi], acc[1][gi]);
            #pragma unroll
            for (int bi = 0; bi < 2; ++bi) {
                float i_ = sigm_(acc[bi][0] + b0I);
                float f_ = sigm_(acc[bi][1] + b0F);
                float g_ = tanh_(acc[bi][2] + b0G);
                float o_ = sigm_(acc[bi][3] + b0O);
                float c  = f_ * c0[bi] + i_ * g_;
                c0[bi] = c;
                g_dec_h0[(s + 1) & 1][b0 + ty * 2 + bi][j] = o_ * tanh_(c);
            }
        }
        grid_barrier();
        {
            u64 acc2[1][4] = {};
            seg16_pipe(a_s2, w_s2, &g_dec_h0[(s + 1) & 1][0][0], H_,
                       dwih1, H_, b0, j0, acc2);
            seg16_pipe(a_s2, w_s2, &g_dec_h1[s & 1][0][0], H_,
                       dwhh1, H_, b0, j0, acc2);
            float acc[2][4];
            #pragma unroll
            for (int gi = 0; gi < 4; ++gi)
                unpack2(acc2[0][gi], acc[0][gi], acc[1][gi]);
            #pragma unroll
            for (int bi = 0; bi < 2; ++bi) {
                float i_ = sigm_(acc[bi][0] + b1I);
                float f_ = sigm_(acc[bi][1] + b1F);
                float g_ = tanh_(acc[bi][2] + b1G);
                float o_ = sigm_(acc[bi][3] + b1O);
                float c  = f_ * c1[bi] + i_ * g_;
                c1[bi] = c;
                g_dec_h1[(s + 1) & 1][b0 + ty * 2 + bi][j] = o_ * tanh_(c);
            }
        }
        grid_barrier();
        {
            const float* h1 = &g_dec_h1[(s + 1) & 1][bid][0];
            float part[MQ_] = {0.f, 0.f, 0.f, 0.f, 0.f};
            for (int k = tid; k < H_; k += 256) {
                float hv = __ldcg(h1 + k);
                #pragma unroll
                for (int q = 0; q < MQ_; ++q)
                    part[q] = fmaf(hv, __ldg(wo + q * H_ + k), part[q]);
            }
            #pragma unroll
            for (int o = 16; o; o >>= 1)
                #pragma unroll
                for (int q = 0; q < MQ_; ++q)
                    part[q] += __shfl_down_sync(0xffffffffu, part[q], o);
            if ((tid & 31) == 0)
                #pragma unroll
                for (int q = 0; q < MQ_; ++q) red[tid >> 5][q] = part[q];
            __syncthreads();
            if (tid < MQ_) {
                float v = __ldg(bo + tid);
                #pragma unroll
                for (int w2 = 0; w2 < 8; ++w2) v += red[w2][tid];
                out[(long)bid * HOR_ * MQ_ + s * MQ_ + tid] = v;
                if (tid == 0) g_decx[bid][0] = v;
            }
            if (s + 1 < HOR_ && tid >= 32 && tid < 32 + DFF_)
                g_decx[bid][tid - 31] =
                    __ldg(fut + (long)bid * HOR_ * DFF_ + (s + 1) * DFF_ + (tid - 32));
        }
        grid_barrier();
    }
}

// ---------------- launcher (7 graph nodes) ----------------
extern "C" void kernel_launch(void* const* d_in, const int* in_sizes, int n_in,
                              void* d_out, int out_size)
{
    int off = (n_in >= 4 && in_sizes[3] == 1) ? 0 : -1;
    const float* X     = (const float*)d_in[0];
    const float* fut   = (const float*)d_in[1];
    const float* ewih0 = (const float*)d_in[4 + off];
    const float* ewhh0 = (const float*)d_in[5 + off];
    const float* eb0   = (const float*)d_in[6 + off];
    const float* ewih1 = (const float*)d_in[7 + off];
    const float* ewhh1 = (const float*)d_in[8 + off];
    const float* eb1   = (const float*)d_in[9 + off];
    const float* dwih0 = (const float*)d_in[10 + off];
    const float* dwhh0 = (const float*)d_in[11 + off];
    const float* db0   = (const float*)d_in[12 + off];
    const float* dwih1 = (const float*)d_in[13 + off];
    const float* dwhh1 = (const float*)d_in[14 + off];
    const float* db1   = (const float*)d_in[15 + off];
    const float* wb    = (const float*)d_in[16 + off];
    const float* bb    = (const float*)d_in[17 + off];
    const float* wo    = (const float*)d_in[18 + off];
    const float* bo    = (const float*)d_in[19 + off];
    float* out = (float*)d_out;

    cudaFuncSetAttribute(enc_mma_persist<0>,
                         cudaFuncAttributeMaxDynamicSharedMemorySize, ENC_SMEM);
    cudaFuncSetAttribute(enc_mma_persist<1>,
                         cudaFuncAttributeMaxDynamicSharedMemorySize, ENC_SMEM);

    gates0_gemm<<<dim3(T_, 2), 256>>>(X, ewih0);
    convB_kernel<<<2048, 256>>>(ewih1);
    enc_mma_persist<0><<<256, 256, ENC_SMEM>>>(ewhh0, eb0);
    gates1_mma<<<dim3(16, 512, 2), 256>>>();
    enc_mma_persist<1><<<256, 256, ENC_SMEM>>>(ewhh1, eb1);
    bridge_kernel<<<dim3(4, 32, 2), 256>>>(wb, bb);
    dec_persist<<<NBLK, 256>>>(X, fut, dwih0, dwhh0, db0,
                               dwih1, dwhh1, db1, wo, bo, out);
}

// round 16
// speedup vs baseline: 1.1329x; 1.1329x over previous
#include <cuda_runtime.h>
#include <cuda_bf16.h>
#include <math.h>
#include <stdint.h>

#define B_   128
#define T_   512
#define H_   512
#define G_   2048
#define DIN_ 8
#define HOR_ 64
#define MQ_  5
#define DFF_ 7
#define NBLK 128

typedef unsigned long long u64;

// ---------------- scratch (device globals; no allocations) ----------------
__device__ float g_gates0[2][T_][B_][G_];    // precomputed layer-0 input gates
__device__ float g_gates1[2][T_][B_][G_];    // precomputed layer-1 input gates
__device__ float g_c[2][2][B_][H_];          // final cell states [layer][dir]
__device__ float g_h0fin[2][B_][H_];         // layer-0 final h per dir (fp32)
__device__ float g_h1fin[2][B_][H_];         // layer-1 final h per dir (fp32)
__device__ float g_dec_h0[2][B_][H_];
__device__ float g_dec_c0[B_][H_];
__device__ float g_dec_h1[2][B_][H_];
__device__ float g_dec_c1[B_][H_];
__device__ float g_decx[B_][DIN_];           // decoder input vector [y_fb, fut]
__device__ unsigned g_bar_cnt;
__device__ unsigned g_bar_gen;

// bf16 hi/lo split activations (enc-L0 h sequence; also gates1_mma's A input)
__device__ __nv_bfloat16 g_Ah[T_ * B_][1024];
__device__ __nv_bfloat16 g_Al[T_ * B_][1024];
// layer-1 h ping-pong, bf16 hi/lo
__device__ __nv_bfloat16 g_h1h[2][2][B_][H_];
__device__ __nv_bfloat16 g_h1l[2][2][B_][H_];
// gates1 weights, bf16 hi/lo
__device__ __nv_bfloat16 g_Bh[2][G_][1024];
__device__ __nv_bfloat16 g_Bl[2][G_][1024];

// ---------------- software grid barrier (R8 mechanism, verbatim) ----------
__device__ __forceinline__ void grid_barrier()
{
    __syncthreads();
    if (threadIdx.x == 0) {
        volatile unsigned* genp = &g_bar_gen;
        unsigned gen = *genp;
        __threadfence();
        if (atomicAdd(&g_bar_cnt, 1u) == NBLK - 1u) {
            g_bar_cnt = 0u;
            __threadfence();
            *genp = gen + 1u;
        } else {
            while (*genp == gen) { }
        }
        __threadfence();
    }
    __syncthreads();
}

// ---------------- packed fp32x2 helpers (decoder SIMT path) ----------------
__device__ __forceinline__ void ffma2(u64& d, u64 a, u64 b) {
    asm("fma.rn.f32x2 %0, %1, %2, %0;" : "+l"(d) : "l"(a), "l"(b));
}
__device__ __forceinline__ u64 bcast2(float v) {
    u64 r;
    asm("mov.b64 %0, {%1, %1};" : "=l"(r) : "f"(v));
    return r;
}
__device__ __forceinline__ void unpack2(u64 v, float& lo, float& hi) {
    asm("mov.b64 {%0, %1}, %2;" : "=f"(lo), "=f"(hi) : "l"(v));
}

// ---------------- fast transcendentals ----------------
__device__ __forceinline__ float sigm_(float x) {
    return __fdividef(1.f, 1.f + __expf(-x));
}
__device__ __forceinline__ float tanh_(float x) {
    return __fdividef(2.f, 1.f + __expf(-2.f * x)) - 1.f;
}

// ---------------- mma.sync / ldmatrix helpers ----------------
__device__ __forceinline__ uint32_t smem_u32(const void* p) {
    uint32_t a;
    asm("{ .reg .u64 t; cvta.to.shared.u64 t, %1; cvt.u32.u64 %0, t; }"
        : "=r"(a) : "l"(p));
    return a;
}
__device__ __forceinline__ void ldsm4(uint32_t a, uint32_t& r0, uint32_t& r1,
                                      uint32_t& r2, uint32_t& r3) {
    asm volatile("ldmatrix.sync.aligned.m8n8.x4.shared.b16 {%0,%1,%2,%3}, [%4];"
                 : "=r"(r0), "=r"(r1), "=r"(r2), "=r"(r3) : "r"(a));
}
__device__ __forceinline__ void mma_bf16(float* c, const uint32_t* a, const uint32_t* b) {
    asm volatile(
        "mma.sync.aligned.m16n8k16.row.col.f32.bf16.bf16.f32 "
        "{%0,%1,%2,%3}, {%4,%5,%6,%7}, {%8,%9}, {%0,%1,%2,%3};"
        : "+f"(c[0]), "+f"(c[1]), "+f"(c[2]), "+f"(c[3])
        : "r"(a[0]), "r"(a[1]), "r"(a[2]), "r"(a[3]), "r"(b[0]), "r"(b[1]));
}

// ---------------- layer-0 input gates: one-shot tiny-K GEMM ----------------
__global__ __launch_bounds__(256) void gates0_gemm(
    const float* __restrict__ X, const float* __restrict__ w_ih)
{
    __shared__ float xs_[B_][DIN_];
    const int t = blockIdx.x, dir = blockIdx.y;
    const int tid = threadIdx.x;
    for (int e = tid; e < B_ * DIN_; e += 256) {
        int b = e >> 3, k = e & 7;
        xs_[b][k] = __ldg(X + ((long)b * T_ + t) * DIN_ + k);
    }
    __syncthreads();
    const float* w = w_ih + (long)dir * G_ * DIN_;
    for (int g = tid; g < G_; g += 256) {
        float4 w0 = *reinterpret_cast<const float4*>(w + g * DIN_);
        float4 w1 = *reinterpret_cast<const float4*>(w + g * DIN_ + 4);
        float* op = &g_gates0[dir][t][0][0];
        for (int b = 0; b < B_; ++b) {
            const float* xb = xs_[b];
            float acc = xb[0] * w0.x + xb[1] * w0.y + xb[2] * w0.z + xb[3] * w0.w
                      + xb[4] * w1.x + xb[5] * w1.y + xb[6] * w1.z + xb[7] * w1.w;
            op[(long)b * G_ + g] = acc;
        }
    }
}

// -------- fp32 -> bf16 hi/lo conversion for gates1 weights ----------------
__global__ __launch_bounds__(256) void convB_kernel(const float* __restrict__ w_ih1)
{
    const long npairs = (long)2 * G_ * 512;
    __nv_bfloat16* bh = &g_Bh[0][0][0];
    __nv_bfloat16* bl = &g_Bl[0][0][0];
    for (long p = (long)blockIdx.x * 256 + threadIdx.x; p < npairs;
         p += (long)gridDim.x * 256) {
        float2 v = *reinterpret_cast<const float2*>(w_ih1 + p * 2);
        __nv_bfloat16 h0 = __float2bfloat16(v.x);
        __nv_bfloat16 l0 = __float2bfloat16(v.x - __bfloat162float(h0));
        __nv_bfloat16 h1 = __float2bfloat16(v.y);
        __nv_bfloat16 l1 = __float2bfloat16(v.y - __bfloat162float(h1));
        *reinterpret_cast<__nv_bfloat162*>(bh + p * 2) = __nv_bfloat162(h0, h1);
        *reinterpret_cast<__nv_bfloat162*>(bl + p * 2) = __nv_bfloat162(l0, l1);
    }
}

// =========== persistent mma-based encoder layer (layer = 0 or 1) ==========
// Block = 64 batch x 64 gate-cols (16 j x 4 gate types), K=512/step.
// W_hh hi/lo resident in SMEM all 512 steps; A (=h) streamed per step in
// 8 double-buffered k-chunks of 64. 8 warps = 4M x 2N (warp: 16 x 32).
#define ESM_W_H 0
#define ESM_W_L 66560
#define ESM_A   133120
#define ESM_AB  9216
#define ESM_C   169984
#define ENC_SMEM 187392

template<int LAYER>
__global__ __launch_bounds__(256, 1) void enc_mma_persist(
    const float* __restrict__ w_hh, const float* __restrict__ bias)
{
    extern __shared__ __align__(16) char esm[];
    __nv_bfloat16* Wh = reinterpret_cast<__nv_bfloat16*>(esm + ESM_W_H);
    __nv_bfloat16* Wl = reinterpret_cast<__nv_bfloat16*>(esm + ESM_W_L);
    float* Cb = reinterpret_cast<float*>(esm + ESM_C);

    const int tid = threadIdx.x, lane = tid & 31, wid = tid >> 5;
    const int warp_m = wid & 3, warp_n = wid >> 2;
    const int bid = blockIdx.x;
    const int dir = bid >> 6, rr = bid & 63;
    const int b0 = (rr >> 5) * 64, j0 = (rr & 31) * 16;

    // ---- one-time W_hh load + hi/lo split into resident smem ----
    const float* wsrc = w_hh + (long)dir * G_ * H_;
    for (int idx = tid; idx < 64 * 512; idx += 256) {
        int n = idx >> 9, k = idx & 511;
        int gc = (n >> 4) * 512 + j0 + (n & 15);
        float v = __ldg(wsrc + (long)gc * H_ + k);
        __nv_bfloat16 h = __float2bfloat16(v);
        Wh[n * 520 + k] = h;
        Wl[n * 520 + k] = __float2bfloat16(v - __bfloat162float(h));
    }

    // ---- per-thread pointwise cell mapping: (pb batch-local, jq j-quad) ----
    const int pb = tid >> 2, jq = tid & 3;
    const float* bp = bias + dir * G_ + j0 + jq * 4;
    float4 bI = __ldg((const float4*)(bp));
    float4 bF = __ldg((const float4*)(bp + 512));
    float4 bG = __ldg((const float4*)(bp + 1024));
    float4 bO = __ldg((const float4*)(bp + 1536));
    float cst[4] = {0.f, 0.f, 0.f, 0.f};

    // ---- ldmatrix lane offsets ----
    uint32_t WhB = smem_u32(Wh), WlB = smem_u32(Wl);
    const uint32_t aRow = (uint32_t)((warp_m * 16 + (lane & 15)) * 144
                                     + (lane >> 4) * 16);
    uint32_t bOff4[2];
    #pragma unroll
    for (int p = 0; p < 2; ++p)
        bOff4[p] = (uint32_t)((warp_n * 32 + (2 * p + ((lane >> 4) & 1)) * 8
                               + (lane & 7)) * 1040
                              + ((lane >> 3) & 1) * 16);

    const float* gatesrc = (LAYER == 0 ? &g_gates0[0][0][0][0]
                                       : &g_gates1[0][0][0][0])
                         + (long)dir * T_ * B_ * G_;
    __syncthreads();

    for (int s = 0; s < T_; ++s) {
        const int t = dir ? (T_ - 1 - s) : s;
        // prefetch gate-init (hidden behind the MMA work)
        const float* gp = gatesrc + ((long)t * B_ + b0 + pb) * G_ + j0 + jq * 4;
        float4 gI = __ldg((const float4*)(gp));
        float4 gF = __ldg((const float4*)(gp + 512));
        float4 gG = __ldg((const float4*)(gp + 1024));
        float4 gO = __ldg((const float4*)(gp + 1536));

        float acc[4][4] = {};
        if (s > 0) {
            const __nv_bfloat16 *pAh, *pAl;
            long apitch;
            if (LAYER == 0) {
                const int tp = dir ? t + 1 : t - 1;
                pAh = &g_Ah[tp * 128 + b0][dir * 512];
                pAl = &g_Al[tp * 128 + b0][dir * 512];
                apitch = 1024;
            } else {
                pAh = &g_h1h[s & 1][dir][b0][0];
                pAl = &g_h1l[s & 1][dir][b0][0];
                apitch = 512;
            }
            uint4 stg[4];
            auto stage = [&](int kc) {
                #pragma unroll
                for (int i = 0; i < 4; ++i) {
                    int idx = tid + i * 256;
                    int term = idx >> 9, rem = idx & 511;
                    int row = rem >> 3, c8 = rem & 7;
                    const __nv_bfloat16* src =
                        (term ? pAl : pAh) + (long)row * apitch + kc * 64 + c8 * 8;
                    stg[i] = __ldcg(reinterpret_cast<const uint4*>(src));
                }
            };
            auto commitA = [&](int buf) {
                #pragma unroll
                for (int i = 0; i < 4; ++i) {
                    int idx = tid + i * 256;
                    int term = idx >> 9, rem = idx & 511;
                    int row = rem >> 3, c8 = rem & 7;
                    *reinterpret_cast<uint4*>(
                        esm + ESM_A + (buf * 2 + term) * ESM_AB + row * 144 + c8 * 16)
                        = stg[i];
                }
            };
            stage(0);
            commitA(0);
            __syncthreads();
            #pragma unroll 1
            for (int kc = 0; kc < 8; ++kc) {
                const int buf = kc & 1;
                if (kc < 7) stage(kc + 1);
                const uint32_t AhB = smem_u32(esm + ESM_A + (buf * 2) * ESM_AB);
                const uint32_t AlB = AhB + ESM_AB;
                #pragma unroll
                for (int ks = 0; ks < 4; ++ks) {
                    const uint32_t wko = kc * 128 + ks * 32;
                    uint32_t ah[4], al[4], bh[4][2], bl[4][2];
                    ldsm4(AhB + aRow + ks * 32, ah[0], ah[1], ah[2], ah[3]);
                    ldsm4(AlB + aRow + ks * 32, al[0], al[1], al[2], al[3]);
                    ldsm4(WhB + bOff4[0] + wko, bh[0][0], bh[0][1], bh[1][0], bh[1][1]);
                    ldsm4(WhB + bOff4[1] + wko, bh[2][0], bh[2][1], bh[3][0], bh[3][1]);
                    ldsm4(WlB + bOff4[0] + wko, bl[0][0], bl[0][1], bl[1][0], bl[1][1]);
                    ldsm4(WlB + bOff4[1] + wko, bl[2][0], bl[2][1], bl[3][0], bl[3][1]);
                    #pragma unroll
                    for (int ni = 0; ni < 4; ++ni) {
                        mma_bf16(acc[ni], ah, bh[ni]);
                        mma_bf16(acc[ni], ah, bl[ni]);
                        mma_bf16(acc[ni], al, bh[ni]);
                    }
                }
                if (kc < 7) {                 // last-iter trailing sync is dead:
                    commitA(buf ^ 1);         // A bufs untouched until next step's
                    __syncthreads();          // barrier; Cb writes are warp-private
                }
            }
        }
        // ---- epilogue: dump acc frags to Cbuf (64 x 64, pitch 68) ----
        {
            const int row = warp_m * 16 + (lane >> 2);
            #pragma unroll
            for (int ni = 0; ni < 4; ++ni) {
                const int col = warp_n * 32 + ni * 8 + (lane & 3) * 2;
                *reinterpret_cast<float2*>(&Cb[row * 68 + col]) =
                    make_float2(acc[ni][0], acc[ni][1]);
                *reinterpret_cast<float2*>(&Cb[(row + 8) * 68 + col]) =
                    make_float2(acc[ni][2], acc[ni][3]);
            }
        }
        __syncthreads();
        // ---- pointwise LSTM cell + h split/write ----
        {
            __align__(8) __nv_bfloat16 hh[4], hl[4];
            float hv[4];
            const float* gIv = (const float*)&gI;
            const float* gFv = (const float*)&gF;
            const float* gGv = (const float*)&gG;
            const float* gOv = (const float*)&gO;
            const float* bIv = (const float*)&bI;
            const float* bFv = (const float*)&bF;
            const float* bGv = (const float*)&bG;
            const float* bOv = (const float*)&bO;
            #pragma unroll
            for (int q = 0; q < 4; ++q) {
                const int jl = jq * 4 + q;
                float iv = Cb[pb * 68 + jl]      + gIv[q] + bIv[q];
                float fv = Cb[pb * 68 + 16 + jl] + gFv[q] + bFv[q];
                float gv = Cb[pb * 68 + 32 + jl] + gGv[q] + bGv[q];
                float ov = Cb[pb * 68 + 48 + jl] + gOv[q] + bOv[q];
                float i_ = sigm_(iv), f_ = sigm_(fv), g_ = tanh_(gv), o_ = sigm_(ov);
                float c = f_ * cst[q] + i_ * g_;
                cst[q] = c;
                float h = o_ * tanh_(c);
                hv[q] = h;
                hh[q] = __float2bfloat16(h);
                hl[q] = __float2bfloat16(h - __bfloat162float(hh[q]));
            }
            if (LAYER == 0) {
                *reinterpret_cast<uint2*>(&g_Ah[t * 128 + b0 + pb][dir * 512 + j0 + jq * 4])
                    = *reinterpret_cast<uint2*>(hh);
                *reinterpret_cast<uint2*>(&g_Al[t * 128 + b0 + pb][dir * 512 + j0 + jq * 4])
                    = *reinterpret_cast<uint2*>(hl);
                if (s == T_ - 1)
                    *reinterpret_cast<float4*>(&g_h0fin[dir][b0 + pb][j0 + jq * 4]) =
                        make_float4(hv[0], hv[1], hv[2], hv[3]);
            } else {
                *reinterpret_cast<uint2*>(&g_h1h[(s + 1) & 1][dir][b0 + pb][j0 + jq * 4])
                    = *reinterpret_cast<uint2*>(hh);
                *reinterpret_cast<uint2*>(&g_h1l[(s + 1) & 1][dir][b0 + pb][j0 + jq * 4])
                    = *reinterpret_cast<uint2*>(hl);
                if (s == T_ - 1)
                    *reinterpret_cast<float4*>(&g_h1fin[dir][b0 + pb][j0 + jq * 4]) =
                        make_float4(hv[0], hv[1], hv[2], hv[3]);
            }
        }
        if (s < T_ - 1) grid_barrier();       // final barrier dead: only own-data
    }                                          // writes follow; launch sync covers
    #pragma unroll
    for (int q = 0; q < 4; ++q)
        g_c[LAYER][dir][b0 + pb][j0 + jq * 4 + q] = cst[q];
}

// ======== gates1 via mma.sync bf16: D[128,128] = A[128,1024] @ W^T =========
#define PITCH 40

__global__ __launch_bounds__(256) void gates1_mma()
{
    __shared__ __align__(16) __nv_bfloat16 smem4[4][128 * PITCH];
    const int tid = threadIdx.x;
    const int wid = tid >> 5, lane = tid & 31;
    const int n0 = blockIdx.x * 128, r0 = blockIdx.y * 128, dir = blockIdx.z;
    const int warp_m = wid & 1, warp_n = wid >> 1;

    const __nv_bfloat16* srcs[4] = {
        &g_Ah[r0][0], &g_Al[r0][0], &g_Bh[dir][n0][0], &g_Bl[dir][n0][0] };
    uint32_t sb[4] = { smem_u32(smem4[0]), smem_u32(smem4[1]),
                       smem_u32(smem4[2]), smem_u32(smem4[3]) };

    uint32_t aOff[4], bOff4[2];
    #pragma unroll
    for (int mi = 0; mi < 4; ++mi)
        aOff[mi] = (uint32_t)((warp_m * 64 + mi * 16 + (lane & 15)) * (PITCH * 2)
                              + (lane >> 4) * 16);
    #pragma unroll
    for (int p = 0; p < 2; ++p)
        bOff4[p] = (uint32_t)((warp_n * 32 + (2 * p + ((lane >> 4) & 1)) * 8
                               + (lane & 7)) * (PITCH * 2)
                              + ((lane >> 3) & 1) * 16);

    uint2 stg[16];
    auto stage = [&](int kbase) {
        #pragma unroll
        for (int i = 0; i < 16; ++i) {
            int idx = i * 256 + tid;
            int tI = idx >> 10, row = (idx >> 3) & 127, c = idx & 7;
            stg[i] = *reinterpret_cast<const uint2*>(
                srcs[tI] + (long)row * 1024 + kbase + c * 4);
        }
    };
    auto commit = [&]() {
        #pragma unroll
        for (int i = 0; i < 16; ++i) {
            int idx = i * 256 + tid;
            int tI = idx >> 10, row = (idx >> 3) & 127, c = idx & 7;
            *reinterpret_cast<uint2*>(&smem4[tI][row * PITCH + c * 4]) = stg[i];
        }
    };

    float acc[4][4][4];
    #pragma unroll
    for (int mi = 0; mi < 4; ++mi)
        #pragma unroll
        for (int ni = 0; ni < 4; ++ni)
            #pragma unroll
            for (int q = 0; q < 4; ++q) acc[mi][ni][q] = 0.f;

    stage(0);
    commit();
    __syncthreads();
    #pragma unroll 1
    for (int kc = 0; kc < 32; ++kc) {
        if (kc < 31) stage((kc + 1) * 32);
        #pragma unroll
        for (int ks = 0; ks < 2; ++ks) {
            const uint32_t kb = ks * 32;
            uint32_t ah[4][4], al[4][4], bh[4][2], bl[4][2];
            #pragma unroll
            for (int mi = 0; mi < 4; ++mi) {
                ldsm4(sb[0] + aOff[mi] + kb, ah[mi][0], ah[mi][1], ah[mi][2], ah[mi][3]);
                ldsm4(sb[1] + aOff[mi] + kb, al[mi][0], al[mi][1], al[mi][2], al[mi][3]);
            }
            ldsm4(sb[2] + bOff4[0] + kb, bh[0][0], bh[0][1], bh[1][0], bh[1][1]);
            ldsm4(sb[2] + bOff4[1] + kb, bh[2][0], bh[2][1], bh[3][0], bh[3][1]);
            ldsm4(sb[3] + bOff4[0] + kb, bl[0][0], bl[0][1], bl[1][0], bl[1][1]);
            ldsm4(sb[3] + bOff4[1] + kb, bl[2][0], bl[2][1], bl[3][0], bl[3][1]);
            #pragma unroll
            for (int mi = 0; mi < 4; ++mi)
                #pragma unroll
                for (int ni = 0; ni < 4; ++ni) {
                    mma_bf16(acc[mi][ni], ah[mi], bh[ni]);
                    mma_bf16(acc[mi][ni], ah[mi], bl[ni]);
                    mma_bf16(acc[mi][ni], al[mi], bh[ni]);
                }
        }
        __syncthreads();
        if (kc < 31) { commit(); __syncthreads(); }
    }

    float* ob = &g_gates1[dir][0][0][0];
    const int group = lane >> 2, tig = lane & 3;
    #pragma unroll
    for (int mi = 0; mi < 4; ++mi) {
        const long row = r0 + warp_m * 64 + mi * 16 + group;
        #pragma unroll
        for (int ni = 0; ni < 4; ++ni) {
            const int col = n0 + warp_n * 32 + ni * 8 + tig * 2;
            *reinterpret_cast<float2*>(ob + row * G_ + col) =
                make_float2(acc[mi][ni][0], acc[mi][ni][1]);
            *reinterpret_cast<float2*>(ob + (row + 8) * G_ + col) =
                make_float2(acc[mi][ni][2], acc[mi][ni][3]);
        }
    }
}

// -------- SIMT segment accumulate, unpipelined (decoder K=8 seg only) -----
template<int BT>
__device__ __forceinline__ void seg_accum(
    float (*a_s)[BT + 4], float (*w_s)[33],
    const float* __restrict__ xp, int xs, int use_ldcg,
    const float* __restrict__ wp, int ws, int K,
    int b0, int j0, u64 acc2[BT / 16][4])
{
    const int tid = threadIdx.x, tx = tid & 31, ty = tid >> 5;
    constexpr int P = BT / 16;
    for (int k0 = 0; k0 < K; k0 += 32) {
        __syncthreads();
        #pragma unroll
        for (int i = 0; i < (BT * 32) / 256; ++i) {
            int e = tid + i * 256;
            int r = e >> 5, kk = e & 31, kg = k0 + kk;
            float v = 0.f;
            if (kg < K) {
                const float* p = xp + (long)(b0 + r) * xs + kg;
                v = use_ldcg ? __ldcg(p) : __ldg(p);
            }
            a_s[kk][r] = v;
        }
        #pragma unroll
        for (int i = 0; i < 16; ++i) {
            int e = tid + i * 256;
            int c = e >> 5, kk = e & 31, kg = k0 + kk;
            float v = 0.f;
            if (kg < K) {
                int gc = j0 + (c >> 5) * 512 + (c & 31);
                v = __ldg(wp + (long)gc * ws + kg);
            }
            w_s[c][kk] = v;
        }
        __syncthreads();
        #pragma unroll
        for (int kk = 0; kk < 32; ++kk) {
            u64 av[P];
            #pragma unroll
            for (int p = 0; p < P; ++p)
                av[p] = *reinterpret_cast<const u64*>(&a_s[kk][ty * (2 * P) + 2 * p]);
            #pragma unroll
            for (int gi = 0; gi < 4; ++gi) {
                u64 wv2 = bcast2(w_s[gi * 32 + tx][kk]);
                #pragma unroll
                for (int p = 0; p < P; ++p)
                    ffma2(acc2[p][gi], av[p], wv2);
            }
        }
    }
}

// -------- pipelined K=512 segment (decoder, BT=16) ------------------------
__device__ __forceinline__ void seg16_pipe(
    float (*a_s)[32][20], float (*w_s)[128][33],
    const float* __restrict__ xp, int xs,
    const float* __restrict__ wp, int ws,
    int b0, int j0, u64 acc2[1][4])
{
    const int tid = threadIdx.x, tx = tid & 31, ty = tid >> 5;
    int aofs[2], gcofs[16];
    #pragma unroll
    for (int i = 0; i < 2; ++i) {
        int e = tid + i * 256;
        aofs[i] = (b0 + (e >> 5)) * xs + (e & 31);
    }
    #pragma unroll
    for (int i = 0; i < 16; ++i) {
        int c = ty + 8 * i;
        gcofs[i] = (j0 + (c >> 5) * 512 + (c & 31)) * ws + tx;
    }
    float ar[2], wr[16];
    auto stage = [&](int kt) {
        const int ko = kt * 32;
        ar[0] = __ldcg(xp + aofs[0] + ko);
        ar[1] = __ldcg(xp + aofs[1] + ko);
        #pragma unroll
        for (int i = 0; i < 16; ++i)
            wr[i] = __ldg(wp + gcofs[i] + ko);
    };
    auto commit = [&](int buf) {
        #pragma unroll
        for (int i = 0; i < 2; ++i) {
            int e = tid + i * 256;
            a_s[buf][e & 31][e >> 5] = ar[i];
        }
        #pragma unroll
        for (int i = 0; i < 16; ++i)
            w_s[buf][ty + 8 * i][tx] = wr[i];
    };
    __syncthreads();
    stage(0);
    commit(0);
    __syncthreads();
    #pragma unroll 1
    for (int kt = 0; kt < 16; ++kt) {
        const int buf = kt & 1;
        if (kt < 15) stage(kt + 1);
        #pragma unroll
        for (int kk = 0; kk < 32; ++kk) {
            u64 av = *reinterpret_cast<const u64*>(&a_s[buf][kk][2 * ty]);
            #pragma unroll
            for (int gi = 0; gi < 4; ++gi) {
                u64 w2 = bcast2(w_s[buf][gi * 32 + tx][kk]);
                ffma2(acc2[0][gi], av, w2);
            }
        }
        if (kt < 15) commit(buf ^ 1);
        __syncthreads();
    }
}

// ---------------- bridge: elu(h/c_flat @ Wbᵀ + bb) -> decoder init ---------
__global__ __launch_bounds__(256) void bridge_kernel(
    const float* __restrict__ wb, const float* __restrict__ bb)
{
    __shared__ float in_s[32][33], w_s2[32][33];
    const int tid = threadIdx.x, tx = tid & 31, ty = tid >> 5;
    const int b0 = blockIdx.x * 32, m0 = blockIdx.y * 32, z = blockIdx.z;
    const float* srcs[4];
    if (z == 0) {
        srcs[0] = &g_h0fin[0][0][0]; srcs[1] = &g_h0fin[1][0][0];
        srcs[2] = &g_h1fin[0][0][0]; srcs[3] = &g_h1fin[1][0][0];
    } else {
        srcs[0] = &g_c[0][0][0][0]; srcs[1] = &g_c[0][1][0][0];
        srcs[2] = &g_c[1][0][0][0]; srcs[3] = &g_c[1][1][0][0];
    }
    float acc[4] = {0.f, 0.f, 0.f, 0.f};
    for (int k0 = 0; k0 < 2048; k0 += 32) {
        __syncthreads();
        const float* src = srcs[k0 >> 9];
        const int kl = k0 & 511;
        #pragma unroll
        for (int i = 0; i < 4; ++i) {
            int e = tid + i * 256;
            int r = e >> 5, kk = e & 31;
            in_s[r][kk] = src[(long)(b0 + r) * H_ + kl + kk];
            w_s2[r][kk] = wb[(long)(m0 + r) * 2048 + k0 + kk];
        }
        __syncthreads();
        #pragma unroll
        for (int kk = 0; kk < 32; ++kk) {
            float wv = w_s2[tx][kk];
            #pragma unroll
            for (int bi = 0; bi < 4; ++bi)
                acc[bi] = fmaf(in_s[ty * 4 + bi][kk], wv, acc[bi]);
        }
    }
    const int m = m0 + tx;
    #pragma unroll
    for (int bi = 0; bi < 4; ++bi) {
        int b = b0 + ty * 4 + bi;
        float v = acc[bi] + bb[m];
        v = (v > 0.f) ? v : expm1f(v);
        if (z == 0) {
            if (m < 512) g_dec_h0[0][b][m] = v; else g_dec_h1[0][b][m - 512] = v;
        } else {
            if (m < 512) g_dec_c0[b][m] = v;    else g_dec_c1[b][m - 512] = v;
        }
    }
}

// ---------------- decoder: persistent, 64 steps ----------------------------
__global__ __launch_bounds__(256, 1) void dec_persist(
    const float* __restrict__ X, const float* __restrict__ fut,
    const float* __restrict__ dwih0, const float* __restrict__ dwhh0,
    const float* __restrict__ db0,
    const float* __restrict__ dwih1, const float* __restrict__ dwhh1,
    const float* __restrict__ db1,
    const float* __restrict__ wo, const float* __restrict__ bo,
    float* __restrict__ out)
{
    __shared__ __align__(16) float a_s2[2][32][20];
    __shared__ __align__(16) float w_s2[2][128][33];
    __shared__ float red[8][MQ_];
    const int bid = blockIdx.x, tid = threadIdx.x;
    const int tx = tid & 31, ty = tid >> 5;
    const int b0 = (bid >> 4) * 16, j0 = (bid & 15) * 32;
    const int j = j0 + tx;

    if (tid < DIN_)
        g_decx[bid][tid] = (tid == 0)
            ? __ldg(X + (long)bid * T_ * DIN_ + (T_ - 1) * DIN_)
            : __ldg(fut + (long)bid * HOR_ * DFF_ + (tid - 1));

    const float b0I = __ldg(db0 + j),        b0F = __ldg(db0 + 512 + j),
                b0G = __ldg(db0 + 1024 + j), b0O = __ldg(db0 + 1536 + j);
    const float b1I = __ldg(db1 + j),        b1F = __ldg(db1 + 512 + j),
                b1G = __ldg(db1 + 1024 + j), b1O = __ldg(db1 + 1536 + j);
    float c0[2], c1[2];
    #pragma unroll
    for (int bi = 0; bi < 2; ++bi) {
        c0[bi] = g_dec_c0[b0 + ty * 2 + bi][j];
        c1[bi] = g_dec_c1[b0 + ty * 2 + bi][j];
    }
    grid_barrier();

    for (int s = 0; s < HOR_; ++s) {
        {
            u64 acc2[1][4] = {};
            seg_accum<16>(a_s2[0], w_s2[0], &g_decx[0][0], DIN_, 1,
                          dwih0, DIN_, DIN_, b0, j0, acc2);
            seg16_pipe(a_s2, w_s2, &g_dec_h0[s & 1][0][0], H_,
                       dwhh0, H_, b0, j0, acc2);
            float acc[2][4];
            #pragma unroll
            for (int gi = 0; gi < 4; ++gi)
                unpack2(acc2[0][gi], acc[0][gi], acc[1][gi]);
            #pragma unroll
            for (int bi = 0; bi < 2; ++bi) {
                float i_ = sigm_(acc[bi][0] + b0I);
                float f_ = sigm_(acc[bi][1] + b0F);
                float g_ = tanh_(acc[bi][2] + b0G);
                float o_ = sigm_(acc[bi][3] + b0O);
                float c  = f_ * c0[bi] + i_ * g_;
                c0[bi] = c;
                g_dec_h0[(s + 1) & 1][b0 + ty * 2 + bi][j] = o_ * tanh_(c);
            }
        }
        grid_barrier();
        {
            u64 acc2[1][4] = {};
            seg16_pipe(a_s2, w_s2, &g_dec_h0[(s + 1) & 1][0][0], H_,
                       dwih1, H_, b0, j0, acc2);
            seg16_pipe(a_s2, w_s2, &g_dec_h1[s & 1][0][0], H_,
                       dwhh1, H_, b0, j0, acc2);
            float acc[2][4];
            #pragma unroll
            for (int gi = 0; gi < 4; ++gi)
                unpack2(acc2[0][gi], acc[0][gi], acc[1][gi]);
            #pragma unroll
            for (int bi = 0; bi < 2; ++bi) {
                float i_ = sigm_(acc[bi][0] + b1I);
                float f_ = sigm_(acc[bi][1] + b1F);
                float g_ = tanh_(acc[bi][2] + b1G);
                float o_ = sigm_(acc[bi][3] + b1O);
                float c  = f_ * c1[bi] + i_ * g_;
                c1[bi] = c;
                g_dec_h1[(s + 1) & 1][b0 + ty * 2 + bi][j] = o_ * tanh_(c);
            }
        }
        grid_barrier();
        {
            const float* h1 = &g_dec_h1[(s + 1) & 1][bid][0];
            float part[MQ_] = {0.f, 0.f, 0.f, 0.f, 0.f};
            for (int k = tid; k < H_; k += 256) {
                float hv = __ldcg(h1 + k);
                #pragma unroll
                for (int q = 0; q < MQ_; ++q)
                    part[q] = fmaf(hv, __ldg(wo + q * H_ + k), part[q]);
            }
            #pragma unroll
            for (int o = 16; o; o >>= 1)
                #pragma unroll
                for (int q = 0; q < MQ_; ++q)
                    part[q] += __shfl_down_sync(0xffffffffu, part[q], o);
            if ((tid & 31) == 0)
                #pragma unroll
                for (int q = 0; q < MQ_; ++q) red[tid >> 5][q] = part[q];
            __syncthreads();
            if (tid < MQ_) {
                float v = __ldg(bo + tid);
                #pragma unroll
                for (int w2 = 0; w2 < 8; ++w2) v += red[w2][tid];
                out[(long)bid * HOR_ * MQ_ + s * MQ_ + tid] = v;
                if (tid == 0) g_decx[bid][0] = v;
            }
            if (s + 1 < HOR_ && tid >= 32 && tid < 32 + DFF_)
                g_decx[bid][tid - 31] =
                    __ldg(fut + (long)bid * HOR_ * DFF_ + (s + 1) * DFF_ + (tid - 32));
        }
        if (s < HOR_ - 1) grid_barrier();     // final barrier dead before exit
    }
}

// ---------------- launcher (7 graph nodes) ----------------
extern "C" void kernel_launch(void* const* d_in, const int* in_sizes, int n_in,
                              void* d_out, int out_size)
{
    int off = (n_in >= 4 && in_sizes[3] == 1) ? 0 : -1;
    const float* X     = (const float*)d_in[0];
    const float* fut   = (const float*)d_in[1];
    const float* ewih0 = (const float*)d_in[4 + off];
    const float* ewhh0 = (const float*)d_in[5 + off];
    const float* eb0   = (const float*)d_in[6 + off];
    const float* ewih1 = (const float*)d_in[7 + off];
    const float* ewhh1 = (const float*)d_in[8 + off];
    const float* eb1   = (const float*)d_in[9 + off];
    const float* dwih0 = (const float*)d_in[10 + off];
    const float* dwhh0 = (const float*)d_in[11 + off];
    const float* db0   = (const float*)d_in[12 + off];
    const float* dwih1 = (const float*)d_in[13 + off];
    const float* dwhh1 = (const float*)d_in[14 + off];
    const float* db1   = (const float*)d_in[15 + off];
    const float* wb    = (const float*)d_in[16 + off];
    const float* bb    = (const float*)d_in[17 + off];
    const float* wo    = (const float*)d_in[18 + off];
    const float* bo    = (const float*)d_in[19 + off];
    float* out = (float*)d_out;

    cudaFuncSetAttribute(enc_mma_persist<0>,
                         cudaFuncAttributeMaxDynamicSharedMemorySize, ENC_SMEM);
    cudaFuncSetAttribute(enc_mma_persist<1>,
                         cudaFuncAttributeMaxDynamicSharedMemorySize, ENC_SMEM);

    gates0_gemm<<<dim3(T_, 2), 256>>>(X, ewih0);
    convB_kernel<<<2048, 256>>>(ewih1);
    enc_mma_persist<0><<<NBLK, 256, ENC_SMEM>>>(ewhh0, eb0);
    gates1_mma<<<dim3(16, 512, 2), 256>>>();
    enc_mma_persist<1><<<NBLK, 256, ENC_SMEM>>>(ewhh1, eb1);
    bridge_kernel<<<dim3(4, 32, 2), 256>>>(wb, bb);
    dec_persist<<<NBLK, 256>>>(X, fut, dwih0, dwhh0, db0,
                               dwih1, dwhh1, db1, wo, bo, out);
}

// round 17
// speedup vs baseline: 1.1448x; 1.0105x over previous
#include <cuda_runtime.h>
#include <cuda_bf16.h>
#include <math.h>
#include <stdint.h>

#define B_   128
#define T_   512
#define H_   512
#define G_   2048
#define DIN_ 8
#define HOR_ 64
#define MQ_  5
#define DFF_ 7
#define NBLK 128

typedef unsigned long long u64;

// ---------------- scratch (device globals; no allocations) ----------------
__device__ float g_gates0[2][T_][B_][G_];    // precomputed layer-0 input gates
__device__ float g_gates1[2][T_][B_][G_];    // precomputed layer-1 input gates
__device__ float g_c[2][2][B_][H_];          // final cell states [layer][dir]
__device__ float g_h0fin[2][B_][H_];         // layer-0 final h per dir (fp32)
__device__ float g_h1fin[2][B_][H_];         // layer-1 final h per dir (fp32)
__device__ float g_dec_h0[2][B_][H_];
__device__ float g_dec_c0[B_][H_];
__device__ float g_dec_h1[2][B_][H_];
__device__ float g_dec_c1[B_][H_];
__device__ float g_ypart[3][B_][MQ_];        // rotating proj accumulators
__device__ unsigned g_bar_cnt;
__device__ unsigned g_bar_gen;

// bf16 hi/lo split activations (enc-L0 h sequence; also gates1_mma's A input)
__device__ __nv_bfloat16 g_Ah[T_ * B_][1024];
__device__ __nv_bfloat16 g_Al[T_ * B_][1024];
// layer-1 h ping-pong, bf16 hi/lo
__device__ __nv_bfloat16 g_h1h[2][2][B_][H_];
__device__ __nv_bfloat16 g_h1l[2][2][B_][H_];
// gates1 weights, bf16 hi/lo
__device__ __nv_bfloat16 g_Bh[2][G_][1024];
__device__ __nv_bfloat16 g_Bl[2][G_][1024];

// ---------------- software grid barrier (R8 mechanism, verbatim) ----------
__device__ __forceinline__ void grid_barrier()
{
    __syncthreads();
    if (threadIdx.x == 0) {
        volatile unsigned* genp = &g_bar_gen;
        unsigned gen = *genp;
        __threadfence();
        if (atomicAdd(&g_bar_cnt, 1u) == NBLK - 1u) {
            g_bar_cnt = 0u;
            __threadfence();
            *genp = gen + 1u;
        } else {
            while (*genp == gen) { }
        }
        __threadfence();
    }
    __syncthreads();
}

// ---------------- packed fp32x2 helpers (decoder SIMT path) ----------------
__device__ __forceinline__ void ffma2(u64& d, u64 a, u64 b) {
    asm("fma.rn.f32x2 %0, %1, %2, %0;" : "+l"(d) : "l"(a), "l"(b));
}
__device__ __forceinline__ u64 bcast2(float v) {
    u64 r;
    asm("mov.b64 %0, {%1, %1};" : "=l"(r) : "f"(v));
    return r;
}
__device__ __forceinline__ void unpack2(u64 v, float& lo, float& hi) {
    asm("mov.b64 {%0, %1}, %2;" : "=f"(lo), "=f"(hi) : "l"(v));
}

// ---------------- fast transcendentals ----------------
__device__ __forceinline__ float sigm_(float x) {
    return __fdividef(1.f, 1.f + __expf(-x));
}
__device__ __forceinline__ float tanh_(float x) {
    return __fdividef(2.f, 1.f + __expf(-2.f * x)) - 1.f;
}

// ---------------- mma.sync / ldmatrix helpers ----------------
__device__ __forceinline__ uint32_t smem_u32(const void* p) {
    uint32_t a;
    asm("{ .reg .u64 t; cvta.to.shared.u64 t, %1; cvt.u32.u64 %0, t; }"
        : "=r"(a) : "l"(p));
    return a;
}
__device__ __forceinline__ void ldsm4(uint32_t a, uint32_t& r0, uint32_t& r1,
                                      uint32_t& r2, uint32_t& r3) {
    asm volatile("ldmatrix.sync.aligned.m8n8.x4.shared.b16 {%0,%1,%2,%3}, [%4];"
                 : "=r"(r0), "=r"(r1), "=r"(r2), "=r"(r3) : "r"(a));
}
__device__ __forceinline__ void mma_bf16(float* c, const uint32_t* a, const uint32_t* b) {
    asm volatile(
        "mma.sync.aligned.m16n8k16.row.col.f32.bf16.bf16.f32 "
        "{%0,%1,%2,%3}, {%4,%5,%6,%7}, {%8,%9}, {%0,%1,%2,%3};"
        : "+f"(c[0]), "+f"(c[1]), "+f"(c[2]), "+f"(c[3])
        : "r"(a[0]), "r"(a[1]), "r"(a[2]), "r"(a[3]), "r"(b[0]), "r"(b[1]));
}

// ---------------- layer-0 input gates: one-shot tiny-K GEMM ----------------
__global__ __launch_bounds__(256) void gates0_gemm(
    const float* __restrict__ X, const float* __restrict__ w_ih)
{
    __shared__ float xs_[B_][DIN_];
    const int t = blockIdx.x, dir = blockIdx.y;
    const int tid = threadIdx.x;
    for (int e = tid; e < B_ * DIN_; e += 256) {
        int b = e >> 3, k = e & 7;
        xs_[b][k] = __ldg(X + ((long)b * T_ + t) * DIN_ + k);
    }
    __syncthreads();
    const float* w = w_ih + (long)dir * G_ * DIN_;
    for (int g = tid; g < G_; g += 256) {
        float4 w0 = *reinterpret_cast<const float4*>(w + g * DIN_);
        float4 w1 = *reinterpret_cast<const float4*>(w + g * DIN_ + 4);
        float* op = &g_gates0[dir][t][0][0];
        for (int b = 0; b < B_; ++b) {
            const float* xb = xs_[b];
            float acc = xb[0] * w0.x + xb[1] * w0.y + xb[2] * w0.z + xb[3] * w0.w
                      + xb[4] * w1.x + xb[5] * w1.y + xb[6] * w1.z + xb[7] * w1.w;
            op[(long)b * G_ + g] = acc;
        }
    }
}

// -------- fp32 -> bf16 hi/lo conversion for gates1 weights ----------------
__global__ __launch_bounds__(256) void convB_kernel(const float* __restrict__ w_ih1)
{
    const long npairs = (long)2 * G_ * 512;
    __nv_bfloat16* bh = &g_Bh[0][0][0];
    __nv_bfloat16* bl = &g_Bl[0][0][0];
    for (long p = (long)blockIdx.x * 256 + threadIdx.x; p < npairs;
         p += (long)gridDim.x * 256) {
        float2 v = *reinterpret_cast<const float2*>(w_ih1 + p * 2);
        __nv_bfloat16 h0 = __float2bfloat16(v.x);
        __nv_bfloat16 l0 = __float2bfloat16(v.x - __bfloat162float(h0));
        __nv_bfloat16 h1 = __float2bfloat16(v.y);
        __nv_bfloat16 l1 = __float2bfloat16(v.y - __bfloat162float(h1));
        *reinterpret_cast<__nv_bfloat162*>(bh + p * 2) = __nv_bfloat162(h0, h1);
        *reinterpret_cast<__nv_bfloat162*>(bl + p * 2) = __nv_bfloat162(l0, l1);
    }
}

// =========== persistent mma-based encoder layer (layer = 0 or 1) ==========
// Block = 64 batch x 64 gate-cols (16 j x 4 gate types), K=512/step.
// W_hh hi/lo resident in SMEM all 512 steps; A (=h) streamed per step in
// 8 double-buffered k-chunks of 64. 8 warps = 4M x 2N (warp: 16 x 32).
#define ESM_W_H 0
#define ESM_W_L 66560
#define ESM_A   133120
#define ESM_AB  9216
#define ESM_C   169984
#define ENC_SMEM 187392

template<int LAYER>
__global__ __launch_bounds__(256, 1) void enc_mma_persist(
    const float* __restrict__ w_hh, const float* __restrict__ bias)
{
    extern __shared__ __align__(16) char esm[];
    __nv_bfloat16* Wh = reinterpret_cast<__nv_bfloat16*>(esm + ESM_W_H);
    __nv_bfloat16* Wl = reinterpret_cast<__nv_bfloat16*>(esm + ESM_W_L);
    float* Cb = reinterpret_cast<float*>(esm + ESM_C);

    const int tid = threadIdx.x, lane = tid & 31, wid = tid >> 5;
    const int warp_m = wid & 3, warp_n = wid >> 2;
    const int bid = blockIdx.x;
    const int dir = bid >> 6, rr = bid & 63;
    const int b0 = (rr >> 5) * 64, j0 = (rr & 31) * 16;

    // ---- one-time W_hh load + hi/lo split into resident smem ----
    const float* wsrc = w_hh + (long)dir * G_ * H_;
    for (int idx = tid; idx < 64 * 512; idx += 256) {
        int n = idx >> 9, k = idx & 511;
        int gc = (n >> 4) * 512 + j0 + (n & 15);
        float v = __ldg(wsrc + (long)gc * H_ + k);
        __nv_bfloat16 h = __float2bfloat16(v);
        Wh[n * 520 + k] = h;
        Wl[n * 520 + k] = __float2bfloat16(v - __bfloat162float(h));
    }

    // ---- per-thread pointwise cell mapping: (pb batch-local, jq j-quad) ----
    const int pb = tid >> 2, jq = tid & 3;
    const float* bp = bias + dir * G_ + j0 + jq * 4;
    float4 bI = __ldg((const float4*)(bp));
    float4 bF = __ldg((const float4*)(bp + 512));
    float4 bG = __ldg((const float4*)(bp + 1024));
    float4 bO = __ldg((const float4*)(bp + 1536));
    float cst[4] = {0.f, 0.f, 0.f, 0.f};

    // ---- ldmatrix lane offsets ----
    uint32_t WhB = smem_u32(Wh), WlB = smem_u32(Wl);
    const uint32_t aRow = (uint32_t)((warp_m * 16 + (lane & 15)) * 144
                                     + (lane >> 4) * 16);
    uint32_t bOff4[2];
    #pragma unroll
    for (int p = 0; p < 2; ++p)
        bOff4[p] = (uint32_t)((warp_n * 32 + (2 * p + ((lane >> 4) & 1)) * 8
                               + (lane & 7)) * 1040
                              + ((lane >> 3) & 1) * 16);

    const float* gatesrc = (LAYER == 0 ? &g_gates0[0][0][0][0]
                                       : &g_gates1[0][0][0][0])
                         + (long)dir * T_ * B_ * G_;
    __syncthreads();

    for (int s = 0; s < T_; ++s) {
        const int t = dir ? (T_ - 1 - s) : s;
        // prefetch gate-init (hidden behind the MMA work)
        const float* gp = gatesrc + ((long)t * B_ + b0 + pb) * G_ + j0 + jq * 4;
        float4 gI = __ldg((const float4*)(gp));
        float4 gF = __ldg((const float4*)(gp + 512));
        float4 gG = __ldg((const float4*)(gp + 1024));
        float4 gO = __ldg((const float4*)(gp + 1536));

        float acc[4][4] = {};
        if (s > 0) {
            const __nv_bfloat16 *pAh, *pAl;
            long apitch;
            if (LAYER == 0) {
                const int tp = dir ? t + 1 : t - 1;
                pAh = &g_Ah[tp * 128 + b0][dir * 512];
                pAl = &g_Al[tp * 128 + b0][dir * 512];
                apitch = 1024;
            } else {
                pAh = &g_h1h[s & 1][dir][b0][0];
                pAl = &g_h1l[s & 1][dir][b0][0];
                apitch = 512;
            }
            uint4 stg[4];
            auto stage = [&](int kc) {
                #pragma unroll
                for (int i = 0; i < 4; ++i) {
                    int idx = tid + i * 256;
                    int term = idx >> 9, rem = idx & 511;
                    int row = rem >> 3, c8 = rem & 7;
                    const __nv_bfloat16* src =
                        (term ? pAl : pAh) + (long)row * apitch + kc * 64 + c8 * 8;
                    stg[i] = __ldcg(reinterpret_cast<const uint4*>(src));
                }
            };
            auto commitA = [&](int buf) {
                #pragma unroll
                for (int i = 0; i < 4; ++i) {
                    int idx = tid + i * 256;
                    int term = idx >> 9, rem = idx & 511;
                    int row = rem >> 3, c8 = rem & 7;
                    *reinterpret_cast<uint4*>(
                        esm + ESM_A + (buf * 2 + term) * ESM_AB + row * 144 + c8 * 16)
                        = stg[i];
                }
            };
            stage(0);
            commitA(0);
            __syncthreads();
            #pragma unroll 1
            for (int kc = 0; kc < 8; ++kc) {
                const int buf = kc & 1;
                if (kc < 7) stage(kc + 1);
                const uint32_t AhB = smem_u32(esm + ESM_A + (buf * 2) * ESM_AB);
                const uint32_t AlB = AhB + ESM_AB;
                #pragma unroll
                for (int ks = 0; ks < 4; ++ks) {
                    const uint32_t wko = kc * 128 + ks * 32;
                    uint32_t ah[4], al[4], bh[4][2], bl[4][2];
                    ldsm4(AhB + aRow + ks * 32, ah[0], ah[1], ah[2], ah[3]);
                    ldsm4(AlB + aRow + ks * 32, al[0], al[1], al[2], al[3]);
                    ldsm4(WhB + bOff4[0] + wko, bh[0][0], bh[0][1], bh[1][0], bh[1][1]);
                    ldsm4(WhB + bOff4[1] + wko, bh[2][0], bh[2][1], bh[3][0], bh[3][1]);
                    ldsm4(WlB + bOff4[0] + wko, bl[0][0], bl[0][1], bl[1][0], bl[1][1]);
                    ldsm4(WlB + bOff4[1] + wko, bl[2][0], bl[2][1], bl[3][0], bl[3][1]);
                    #pragma unroll
                    for (int ni = 0; ni < 4; ++ni) {
                        mma_bf16(acc[ni], ah, bh[ni]);
                        mma_bf16(acc[ni], ah, bl[ni]);
                        mma_bf16(acc[ni], al, bh[ni]);
                    }
                }
                if (kc < 7) {
                    commitA(buf ^ 1);
                    __syncthreads();
                }
            }
        }
        // ---- epilogue: dump acc frags to Cbuf (64 x 64, pitch 68) ----
        {
            const int row = warp_m * 16 + (lane >> 2);
            #pragma unroll
            for (int ni = 0; ni < 4; ++ni) {
                const int col = warp_n * 32 + ni * 8 + (lane & 3) * 2;
                *reinterpret_cast<float2*>(&Cb[row * 68 + col]) =
                    make_float2(acc[ni][0], acc[ni][1]);
                *reinterpret_cast<float2*>(&Cb[(row + 8) * 68 + col]) =
                    make_float2(acc[ni][2], acc[ni][3]);
            }
        }
        __syncthreads();
        // ---- pointwise LSTM cell + h split/write ----
        {
            __align__(8) __nv_bfloat16 hh[4], hl[4];
            float hv[4];
            const float* gIv = (const float*)&gI;
            const float* gFv = (const float*)&gF;
            const float* gGv = (const float*)&gG;
            const float* gOv = (const float*)&gO;
            const float* bIv = (const float*)&bI;
            const float* bFv = (const float*)&bF;
            const float* bGv = (const float*)&bG;
            const float* bOv = (const float*)&bO;
            #pragma unroll
            for (int q = 0; q < 4; ++q) {
                const int jl = jq * 4 + q;
                float iv = Cb[pb * 68 + jl]      + gIv[q] + bIv[q];
                float fv = Cb[pb * 68 + 16 + jl] + gFv[q] + bFv[q];
                float gv = Cb[pb * 68 + 32 + jl] + gGv[q] + bGv[q];
                float ov = Cb[pb * 68 + 48 + jl] + gOv[q] + bOv[q];
                float i_ = sigm_(iv), f_ = sigm_(fv), g_ = tanh_(gv), o_ = sigm_(ov);
                float c = f_ * cst[q] + i_ * g_;
                cst[q] = c;
                float h = o_ * tanh_(c);
                hv[q] = h;
                hh[q] = __float2bfloat16(h);
                hl[q] = __float2bfloat16(h - __bfloat162float(hh[q]));
            }
            if (LAYER == 0) {
                *reinterpret_cast<uint2*>(&g_Ah[t * 128 + b0 + pb][dir * 512 + j0 + jq * 4])
                    = *reinterpret_cast<uint2*>(hh);
                *reinterpret_cast<uint2*>(&g_Al[t * 128 + b0 + pb][dir * 512 + j0 + jq * 4])
                    = *reinterpret_cast<uint2*>(hl);
                if (s == T_ - 1)
                    *reinterpret_cast<float4*>(&g_h0fin[dir][b0 + pb][j0 + jq * 4]) =
                        make_float4(hv[0], hv[1], hv[2], hv[3]);
            } else {
                *reinterpret_cast<uint2*>(&g_h1h[(s + 1) & 1][dir][b0 + pb][j0 + jq * 4])
                    = *reinterpret_cast<uint2*>(hh);
                *reinterpret_cast<uint2*>(&g_h1l[(s + 1) & 1][dir][b0 + pb][j0 + jq * 4])
                    = *reinterpret_cast<uint2*>(hl);
                if (s == T_ - 1)
                    *reinterpret_cast<float4*>(&g_h1fin[dir][b0 + pb][j0 + jq * 4]) =
                        make_float4(hv[0], hv[1], hv[2], hv[3]);
            }
        }
        if (s < T_ - 1) grid_barrier();
    }
    #pragma unroll
    for (int q = 0; q < 4; ++q)
        g_c[LAYER][dir][b0 + pb][j0 + jq * 4 + q] = cst[q];
}

// ======== gates1 via mma.sync bf16: D[128,128] = A[128,1024] @ W^T =========
#define PITCH 40

__global__ __launch_bounds__(256) void gates1_mma()
{
    __shared__ __align__(16) __nv_bfloat16 smem4[4][128 * PITCH];
    const int tid = threadIdx.x;
    const int wid = tid >> 5, lane = tid & 31;
    const int n0 = blockIdx.x * 128, r0 = blockIdx.y * 128, dir = blockIdx.z;
    const int warp_m = wid & 1, warp_n = wid >> 1;

    const __nv_bfloat16* srcs[4] = {
        &g_Ah[r0][0], &g_Al[r0][0], &g_Bh[dir][n0][0], &g_Bl[dir][n0][0] };
    uint32_t sb[4] = { smem_u32(smem4[0]), smem_u32(smem4[1]),
                       smem_u32(smem4[2]), smem_u32(smem4[3]) };

    uint32_t aOff[4], bOff4[2];
    #pragma unroll
    for (int mi = 0; mi < 4; ++mi)
        aOff[mi] = (uint32_t)((warp_m * 64 + mi * 16 + (lane & 15)) * (PITCH * 2)
                              + (lane >> 4) * 16);
    #pragma unroll
    for (int p = 0; p < 2; ++p)
        bOff4[p] = (uint32_t)((warp_n * 32 + (2 * p + ((lane >> 4) & 1)) * 8
                               + (lane & 7)) * (PITCH * 2)
                              + ((lane >> 3) & 1) * 16);

    uint2 stg[16];
    auto stage = [&](int kbase) {
        #pragma unroll
        for (int i = 0; i < 16; ++i) {
            int idx = i * 256 + tid;
            int tI = idx >> 10, row = (idx >> 3) & 127, c = idx & 7;
            stg[i] = *reinterpret_cast<const uint2*>(
                srcs[tI] + (long)row * 1024 + kbase + c * 4);
        }
    };
    auto commit = [&]() {
        #pragma unroll
        for (int i = 0; i < 16; ++i) {
            int idx = i * 256 + tid;
            int tI = idx >> 10, row = (idx >> 3) & 127, c = idx & 7;
            *reinterpret_cast<uint2*>(&smem4[tI][row * PITCH + c * 4]) = stg[i];
        }
    };

    float acc[4][4][4];
    #pragma unroll
    for (int mi = 0; mi < 4; ++mi)
        #pragma unroll
        for (int ni = 0; ni < 4; ++ni)
            #pragma unroll
            for (int q = 0; q < 4; ++q) acc[mi][ni][q] = 0.f;

    stage(0);
    commit();
    __syncthreads();
    #pragma unroll 1
    for (int kc = 0; kc < 32; ++kc) {
        if (kc < 31) stage((kc + 1) * 32);
        #pragma unroll
        for (int ks = 0; ks < 2; ++ks) {
            const uint32_t kb = ks * 32;
            uint32_t ah[4][4], al[4][4], bh[4][2], bl[4][2];
            #pragma unroll
            for (int mi = 0; mi < 4; ++mi) {
                ldsm4(sb[0] + aOff[mi] + kb, ah[mi][0], ah[mi][1], ah[mi][2], ah[mi][3]);
                ldsm4(sb[1] + aOff[mi] + kb, al[mi][0], al[mi][1], al[mi][2], al[mi][3]);
            }
            ldsm4(sb[2] + bOff4[0] + kb, bh[0][0], bh[0][1], bh[1][0], bh[1][1]);
            ldsm4(sb[2] + bOff4[1] + kb, bh[2][0], bh[2][1], bh[3][0], bh[3][1]);
            ldsm4(sb[3] + bOff4[0] + kb, bl[0][0], bl[0][1], bl[1][0], bl[1][1]);
            ldsm4(sb[3] + bOff4[1] + kb, bl[2][0], bl[2][1], bl[3][0], bl[3][1]);
            #pragma unroll
            for (int mi = 0; mi < 4; ++mi)
                #pragma unroll
                for (int ni = 0; ni < 4; ++ni) {
                    mma_bf16(acc[mi][ni], ah[mi], bh[ni]);
                    mma_bf16(acc[mi][ni], ah[mi], bl[ni]);
                    mma_bf16(acc[mi][ni], al[mi], bh[ni]);
                }
        }
        __syncthreads();
        if (kc < 31) { commit(); __syncthreads(); }
    }

    float* ob = &g_gates1[dir][0][0][0];
    const int group = lane >> 2, tig = lane & 3;
    #pragma unroll
    for (int mi = 0; mi < 4; ++mi) {
        const long row = r0 + warp_m * 64 + mi * 16 + group;
        #pragma unroll
        for (int ni = 0; ni < 4; ++ni) {
            const int col = n0 + warp_n * 32 + ni * 8 + tig * 2;
            *reinterpret_cast<float2*>(ob + row * G_ + col) =
                make_float2(acc[mi][ni][0], acc[mi][ni][1]);
            *reinterpret_cast<float2*>(ob + (row + 8) * G_ + col) =
                make_float2(acc[mi][ni][2], acc[mi][ni][3]);
        }
    }
}

// -------- pipelined K=512 segment (decoder, BT=16) ------------------------
__device__ __forceinline__ void seg16_pipe(
    float (*a_s)[32][20], float (*w_s)[128][33],
    const float* __restrict__ xp, int xs,
    const float* __restrict__ wp, int ws,
    int b0, int j0, u64 acc2[1][4])
{
    const int tid = threadIdx.x, tx = tid & 31, ty = tid >> 5;
    int aofs[2], gcofs[16];
    #pragma unroll
    for (int i = 0; i < 2; ++i) {
        int e = tid + i * 256;
        aofs[i] = (b0 + (e >> 5)) * xs + (e & 31);
    }
    #pragma unroll
    for (int i = 0; i < 16; ++i) {
        int c = ty + 8 * i;
        gcofs[i] = (j0 + (c >> 5) * 512 + (c & 31)) * ws + tx;
    }
    float ar[2], wr[16];
    auto stage = [&](int kt) {
        const int ko = kt * 32;
        ar[0] = __ldcg(xp + aofs[0] + ko);
        ar[1] = __ldcg(xp + aofs[1] + ko);
        #pragma unroll
        for (int i = 0; i < 16; ++i)
            wr[i] = __ldg(wp + gcofs[i] + ko);
    };
    auto commit = [&](int buf) {
        #pragma unroll
        for (int i = 0; i < 2; ++i) {
            int e = tid + i * 256;
            a_s[buf][e & 31][e >> 5] = ar[i];
        }
        #pragma unroll
        for (int i = 0; i < 16; ++i)
            w_s[buf][ty + 8 * i][tx] = wr[i];
    };
    __syncthreads();
    stage(0);
    commit(0);
    __syncthreads();
    #pragma unroll 1
    for (int kt = 0; kt < 16; ++kt) {
        const int buf = kt & 1;
        if (kt < 15) stage(kt + 1);
        #pragma unroll
        for (int kk = 0; kk < 32; ++kk) {
            u64 av = *reinterpret_cast<const u64*>(&a_s[buf][kk][2 * ty]);
            #pragma unroll
            for (int gi = 0; gi < 4; ++gi) {
                u64 w2 = bcast2(w_s[buf][gi * 32 + tx][kk]);
                ffma2(acc2[0][gi], av, w2);
            }
        }
        if (kt < 15) commit(buf ^ 1);
        __syncthreads();
    }
}

// ---------------- bridge: elu(h/c_flat @ Wbᵀ + bb) -> decoder init ---------
__global__ __launch_bounds__(256) void bridge_kernel(
    const float* __restrict__ wb, const float* __restrict__ bb)
{
    __shared__ float in_s[32][33], w_s2[32][33];
    const int tid = threadIdx.x, tx = tid & 31, ty = tid >> 5;
    const int b0 = blockIdx.x * 32, m0 = blockIdx.y * 32, z = blockIdx.z;
    const float* srcs[4];
    if (z == 0) {
        srcs[0] = &g_h0fin[0][0][0]; srcs[1] = &g_h0fin[1][0][0];
        srcs[2] = &g_h1fin[0][0][0]; srcs[3] = &g_h1fin[1][0][0];
    } else {
        srcs[0] = &g_c[0][0][0][0]; srcs[1] = &g_c[0][1][0][0];
        srcs[2] = &g_c[1][0][0][0]; srcs[3] = &g_c[1][1][0][0];
    }
    float acc[4] = {0.f, 0.f, 0.f, 0.f};
    for (int k0 = 0; k0 < 2048; k0 += 32) {
        __syncthreads();
        const float* src = srcs[k0 >> 9];
        const int kl = k0 & 511;
        #pragma unroll
        for (int i = 0; i < 4; ++i) {
            int e = tid + i * 256;
            int r = e >> 5, kk = e & 31;
            in_s[r][kk] = src[(long)(b0 + r) * H_ + kl + kk];
            w_s2[r][kk] = wb[(long)(m0 + r) * 2048 + k0 + kk];
        }
        __syncthreads();
        #pragma unroll
        for (int kk = 0; kk < 32; ++kk) {
            float wv = w_s2[tx][kk];
            #pragma unroll
            for (int bi = 0; bi < 4; ++bi)
                acc[bi] = fmaf(in_s[ty * 4 + bi][kk], wv, acc[bi]);
        }
    }
    const int m = m0 + tx;
    #pragma unroll
    for (int bi = 0; bi < 4; ++bi) {
        int b = b0 + ty * 4 + bi;
        float v = acc[bi] + bb[m];
        v = (v > 0.f) ? v : expm1f(v);
        if (z == 0) {
            if (m < 512) g_dec_h0[0][b][m] = v; else g_dec_h1[0][b][m - 512] = v;
        } else {
            if (m < 512) g_dec_c0[b][m] = v;    else g_dec_c1[b][m - 512] = v;
        }
    }
}

// ---------------- decoder: persistent, 64 steps, 2 barriers/step -----------
// Proj fused into cell1 phase: per-CTA partial dot-products -> atomicAdd into
// rotating g_ypart[s%3]; next step's cell0 reads feedback + writes out[s-1].
__global__ __launch_bounds__(256, 1) void dec_persist(
    const float* __restrict__ X, const float* __restrict__ fut,
    const float* __restrict__ dwih0, const float* __restrict__ dwhh0,
    const float* __restrict__ db0,
    const float* __restrict__ dwih1, const float* __restrict__ dwhh1,
    const float* __restrict__ db1,
    const float* __restrict__ wo, const float* __restrict__ bo,
    float* __restrict__ out)
{
    __shared__ __align__(16) float a_s2[2][32][20];
    __shared__ __align__(16) float w_s2[2][128][33];
    const int bid = blockIdx.x, tid = threadIdx.x;
    const int tx = tid & 31, ty = tid >> 5;
    const int b0 = (bid >> 4) * 16, j0 = (bid & 15) * 32;
    const int j = j0 + tx;
    const int bA = b0 + ty * 2, bB = bA + 1;

    // replay-safe init of rotating proj accumulators
    if (bid == 0)
        for (int i = tid; i < 3 * B_ * MQ_; i += 256)
            (&g_ypart[0][0][0])[i] = 0.f;

    const float b0I = __ldg(db0 + j),        b0F = __ldg(db0 + 512 + j),
                b0G = __ldg(db0 + 1024 + j), b0O = __ldg(db0 + 1536 + j);
    const float b1I = __ldg(db1 + j),        b1F = __ldg(db1 + 512 + j),
                b1G = __ldg(db1 + 1024 + j), b1O = __ldg(db1 + 1536 + j);
    // one-time weight preloads: W_ih0 rows (K=8) + w_out column
    float wih0r[4][8];
    #pragma unroll
    for (int gi = 0; gi < 4; ++gi)
        #pragma unroll
        for (int k = 0; k < 8; ++k)
            wih0r[gi][k] = __ldg(dwih0 + (long)(gi * 512 + j) * DIN_ + k);
    float wor[MQ_];
    #pragma unroll
    for (int q = 0; q < MQ_; ++q) wor[q] = __ldg(wo + q * H_ + j);
    const float bo0 = __ldg(bo);

    float c0[2], c1[2];
    #pragma unroll
    for (int bi = 0; bi < 2; ++bi) {
        c0[bi] = g_dec_c0[b0 + ty * 2 + bi][j];
        c1[bi] = g_dec_c1[b0 + ty * 2 + bi][j];
    }
    grid_barrier();

    for (int s = 0; s < HOR_; ++s) {
        // ===== phase A: out[s-1] write, feedback, K=8 gates, cell0 =====
        {
            float yA, yB;
            if (s == 0) {
                yA = __ldg(X + (long)bA * T_ * DIN_ + (T_ - 1) * DIN_);
                yB = __ldg(X + (long)bB * T_ * DIN_ + (T_ - 1) * DIN_);
            } else {
                yA = g_ypart[(s - 1) % 3][bA][0] + bo0;
                yB = g_ypart[(s - 1) % 3][bB][0] + bo0;
            }
            if (s >= 1 && (bid & 15) == 0 && tid < 16 * MQ_) {
                int b = b0 + tid / MQ_, q = tid % MQ_;
                out[(long)b * HOR_ * MQ_ + (s - 1) * MQ_ + q] =
                    g_ypart[(s - 1) % 3][b][q] + __ldg(bo + q);
            }
            float xA[8], xB[8];
            xA[0] = yA; xB[0] = yB;
            const float* fA = fut + (long)bA * HOR_ * DFF_ + s * DFF_;
            const float* fB = fut + (long)bB * HOR_ * DFF_ + s * DFF_;
            #pragma unroll
            for (int k = 0; k < DFF_; ++k) {
                xA[k + 1] = __ldg(fA + k);
                xB[k + 1] = __ldg(fB + k);
            }
            float xg[2][4];
            #pragma unroll
            for (int gi = 0; gi < 4; ++gi) {
                float sA = 0.f, sB = 0.f;
                #pragma unroll
                for (int k = 0; k < 8; ++k) {
                    sA = fmaf(xA[k], wih0r[gi][k], sA);
                    sB = fmaf(xB[k], wih0r[gi][k], sB);
                }
                xg[0][gi] = sA; xg[1][gi] = sB;
            }
            u64 acc2[1][4] = {};
            seg16_pipe(a_s2, w_s2, &g_dec_h0[s & 1][0][0], H_,
                       dwhh0, H_, b0, j0, acc2);
            float acc[2][4];
            #pragma unroll
            for (int gi = 0; gi < 4; ++gi)
                unpack2(acc2[0][gi], acc[0][gi], acc[1][gi]);
            #pragma unroll
            for (int bi = 0; bi < 2; ++bi) {
                float i_ = sigm_(acc[bi][0] + xg[bi][0] + b0I);
                float f_ = sigm_(acc[bi][1] + xg[bi][1] + b0F);
                float g_ = tanh_(acc[bi][2] + xg[bi][2] + b0G);
                float o_ = sigm_(acc[bi][3] + xg[bi][3] + b0O);
                float c  = f_ * c0[bi] + i_ * g_;
                c0[bi] = c;
                g_dec_h0[(s + 1) & 1][b0 + ty * 2 + bi][j] = o_ * tanh_(c);
            }
        }
        grid_barrier();
        // ===== phase B: cell1 + proj partials + rotate-zero ============
        {
            u64 acc2[1][4] = {};
            seg16_pipe(a_s2, w_s2, &g_dec_h0[(s + 1) & 1][0][0], H_,
                       dwih1, H_, b0, j0, acc2);
            seg16_pipe(a_s2, w_s2, &g_dec_h1[s & 1][0][0], H_,
                       dwhh1, H_, b0, j0, acc2);
            float acc[2][4];
            #pragma unroll
            for (int gi = 0; gi < 4; ++gi)
                unpack2(acc2[0][gi], acc[0][gi], acc[1][gi]);
            float hv[2];
            #pragma unroll
            for (int bi = 0; bi < 2; ++bi) {
                float i_ = sigm_(acc[bi][0] + b1I);
                float f_ = sigm_(acc[bi][1] + b1F);
                float g_ = tanh_(acc[bi][2] + b1G);
                float o_ = sigm_(acc[bi][3] + b1O);
                float c  = f_ * c1[bi] + i_ * g_;
                c1[bi] = c;
                hv[bi] = o_ * tanh_(c);
                g_dec_h1[(s + 1) & 1][b0 + ty * 2 + bi][j] = hv[bi];
            }
            // proj partials over this CTA's 32 columns (warp shuffle reduce)
            float pA[MQ_], pB[MQ_];
            #pragma unroll
            for (int q = 0; q < MQ_; ++q) {
                pA[q] = hv[0] * wor[q];
                pB[q] = hv[1] * wor[q];
            }
            #pragma unroll
            for (int o = 16; o; o >>= 1)
                #pragma unroll
                for (int q = 0; q < MQ_; ++q) {
                    pA[q] += __shfl_down_sync(0xffffffffu, pA[q], o);
                    pB[q] += __shfl_down_sync(0xffffffffu, pB[q], o);
                }
            if (tx == 0) {
                #pragma unroll
                for (int q = 0; q < MQ_; ++q) {
                    atomicAdd(&g_ypart[s % 3][bA][q], pA[q]);
                    atomicAdd(&g_ypart[s % 3][bB][q], pB[q]);
                }
            }
            // zero the slot used 2 steps from now (last read 2 barriers ago)
            if ((bid & 15) == 1 && tid < 16 * MQ_) {
                int b = b0 + tid / MQ_, q = tid % MQ_;
                g_ypart[(s + 1) % 3][b][q] = 0.f;
            }
        }
        grid_barrier();
    }
    // tail: write out for the last step
    if ((bid & 15) == 0 && tid < 16 * MQ_) {
        int b = b0 + tid / MQ_, q = tid % MQ_;
        out[(long)b * HOR_ * MQ_ + (HOR_ - 1) * MQ_ + q] =
            g_ypart[(HOR_ - 1) % 3][b][q] + __ldg(bo + q);
    }
}

// ---------------- launcher (7 graph nodes) ----------------
extern "C" void kernel_launch(void* const* d_in, const int* in_sizes, int n_in,
                              void* d_out, int out_size)
{
    int off = (n_in >= 4 && in_sizes[3] == 1) ? 0 : -1;
    const float* X     = (const float*)d_in[0];
    const float* fut   = (const float*)d_in[1];
    const float* ewih0 = (const float*)d_in[4 + off];
    const float* ewhh0 = (const float*)d_in[5 + off];
    const float* eb0   = (const float*)d_in[6 + off];
    const float* ewih1 = (const float*)d_in[7 + off];
    const float* ewhh1 = (const float*)d_in[8 + off];
    const float* eb1   = (const float*)d_in[9 + off];
    const float* dwih0 = (const float*)d_in[10 + off];
    const float* dwhh0 = (const float*)d_in[11 + off];
    const float* db0   = (const float*)d_in[12 + off];
    const float* dwih1 = (const float*)d_in[13 + off];
    const float* dwhh1 = (const float*)d_in[14 + off];
    const float* db1   = (const float*)d_in[15 + off];
    const float* wb    = (const float*)d_in[16 + off];
    const float* bb    = (const float*)d_in[17 + off];
    const float* wo    = (const float*)d_in[18 + off];
    const float* bo    = (const float*)d_in[19 + off];
    float* out = (float*)d_out;

    cudaFuncSetAttribute(enc_mma_persist<0>,
                         cudaFuncAttributeMaxDynamicSharedMemorySize, ENC_SMEM);
    cudaFuncSetAttribute(enc_mma_persist<1>,
                         cudaFuncAttributeMaxDynamicSharedMemorySize, ENC_SMEM);

    gates0_gemm<<<dim3(T_, 2), 256>>>(X, ewih0);
    convB_kernel<<<2048, 256>>>(ewih1);
    enc_mma_persist<0><<<NBLK, 256, ENC_SMEM>>>(ewhh0, eb0);
    gates1_mma<<<dim3(16, 512, 2), 256>>>();
    enc_mma_persist<1><<<NBLK, 256, ENC_SMEM>>>(ewhh1, eb1);
    bridge_kernel<<<dim3(4, 32, 2), 256>>>(wb, bb);
    dec_persist<<<NBLK, 256>>>(X, fut, dwih0, dwhh0, db0,
                               dwih1, dwhh1, db1, wo, bo, out);
}